// round 7
// baseline (speedup 1.0000x reference)
#include <cuda_runtime.h>
#include <cuda_bf16.h>
#include <cstdint>
#include <math.h>

#define DI __device__ __forceinline__

constexpr int TOK = 32768;           // 8 * 64 * 64
constexpr float EPS = 1e-5f;
constexpr int CH = 32;               // tokens per chunk
constexpr int CHUNKS = TOK / CH;     // 1024

// ---------------------------------------------------------------------------
// Device scratch
// ---------------------------------------------------------------------------
__device__ __align__(16) __nv_bfloat16 g_xt_hi[TOK * 128], g_xt_lo[TOK * 128];
__device__ __align__(16) __nv_bfloat16 g_a2_hi[TOK * 128], g_a2_lo[TOK * 128];
__device__ __align__(16) float         g_vpom[TOK * 192];
__device__ __align__(16) __nv_bfloat16 g_dcn_hi[TOK * 128], g_dcn_lo[TOK * 128];
__device__ __align__(16) float         g_op[TOK * 128];
__device__ __align__(16) __nv_bfloat16 g_ot_hi[TOK * 128], g_ot_lo[TOK * 128];

__device__ __align__(16) __nv_bfloat16 g_w1h[128 * 128], g_w1l[128 * 128];
__device__ __align__(16) __nv_bfloat16 g_w2h[192 * 128], g_w2l[192 * 128];
__device__ __align__(16) __nv_bfloat16 g_w4h[128 * 128], g_w4l[128 * 128];
__device__ __align__(16) __nv_bfloat16 g_w5h[128 * 128], g_w5l[128 * 128];
__device__ float g_bias0[128], g_bias1[128], g_bcat[192], g_zero[192];

// ---------------------------------------------------------------------------
// Helpers
// ---------------------------------------------------------------------------
DI uint32_t smem_u32(const void* p) {
    uint32_t a;
    asm("{ .reg .u64 t; cvta.to.shared.u64 t, %1; cvt.u32.u64 %0, t; }" : "=r"(a) : "l"(p));
    return a;
}

DI void cpa16(uint32_t dst, const void* src) {
    asm volatile("{ .reg .u64 g; cvta.to.global.u64 g, %1; "
                 "cp.async.cg.shared.global [%0], [g], 16; }"
                 :: "r"(dst), "l"(src));
}
DI void cpa_commit() { asm volatile("cp.async.commit_group;" ::: "memory"); }
DI void cpa_wait0() { asm volatile("cp.async.wait_group 0;" ::: "memory"); }
DI void cpa_wait1() { asm volatile("cp.async.wait_group 1;" ::: "memory"); }

DI void ldsm4(uint32_t (&r)[4], uint32_t addr) {
    asm volatile("ldmatrix.sync.aligned.m8n8.x4.shared.b16 {%0,%1,%2,%3}, [%4];"
                 : "=r"(r[0]), "=r"(r[1]), "=r"(r[2]), "=r"(r[3]) : "r"(addr));
}

DI void mma16816(float (&d)[4], const uint32_t (&a)[4], uint32_t b0, uint32_t b1) {
    asm volatile("mma.sync.aligned.m16n8k16.row.col.f32.bf16.bf16.f32 "
                 "{%0,%1,%2,%3}, {%4,%5,%6,%7}, {%8,%9}, {%0,%1,%2,%3};"
                 : "+f"(d[0]), "+f"(d[1]), "+f"(d[2]), "+f"(d[3])
                 : "r"(a[0]), "r"(a[1]), "r"(a[2]), "r"(a[3]), "r"(b0), "r"(b1));
}

// XOR-swizzled tile: row stride 256 B (128 bf16), 16B chunk c -> c ^ (row&7)
DI uint32_t tile_off(int r, int chunk) { return (uint32_t)(r * 256 + ((chunk ^ (r & 7)) << 4)); }

DI uint32_t pk(float a, float b) {
    __nv_bfloat16 ha = __float2bfloat16(a), hb = __float2bfloat16(b);
    return ((uint32_t)__bfloat16_as_ushort(hb) << 16) | (uint32_t)__bfloat16_as_ushort(ha);
}
DI uint32_t pksplit(float a, float b, float& ra, float& rb) {
    __nv_bfloat16 ha = __float2bfloat16(a), hb = __float2bfloat16(b);
    ra = a - __bfloat162float(ha);
    rb = b - __bfloat162float(hb);
    return ((uint32_t)__bfloat16_as_ushort(hb) << 16) | (uint32_t)__bfloat16_as_ushort(ha);
}

// Async-load one 32-token A chunk (hi at dst, lo at dst+8192), swizzled.
DI void load_chunkA(uint32_t dst, const __nv_bfloat16* __restrict__ Ah,
                    const __nv_bfloat16* __restrict__ Al, size_t m0, int t)
{
    const uint4* sh_ = (const uint4*)(Ah + m0 * 128);
    const uint4* sl_ = (const uint4*)(Al + m0 * 128);
    for (int i = t; i < 512; i += 256) {
        int r = i >> 4, c = i & 15;
        uint32_t o = tile_off(r, c);
        cpa16(dst + o, sh_ + i);
        cpa16(dst + 8192 + o, sl_ + i);
    }
}

// ---------------------------------------------------------------------------
// Weight prep: fold BN, transpose to [n][k], split bf16 hi/lo
// ---------------------------------------------------------------------------
__global__ void prep_weights(const float* __restrict__ w_pw0, const float* __restrict__ w_pw1,
                             const float* __restrict__ w_vp,  const float* __restrict__ w_om,
                             const float* __restrict__ w_op,
                             const float* __restrict__ bn1_g, const float* __restrict__ bn1_v,
                             const float* __restrict__ bn2_g, const float* __restrict__ bn2_v)
{
    int idx = blockIdx.x * blockDim.x + threadIdx.x;
    if (idx >= 73728) return;
    float w; __nv_bfloat16 *H, *L; int off;
    if (idx < 16384) {
        int k = idx & 127;
        w = w_pw0[idx] * bn1_g[k] * rsqrtf(bn1_v[k] + EPS);
        H = g_w1h; L = g_w1l; off = idx;
    } else if (idx < 32768) {
        int j = idx - 16384; int k = j & 127;
        w = w_pw1[j] * bn2_g[k] * rsqrtf(bn2_v[k] + EPS);
        H = g_w5h; L = g_w5l; off = j;
    } else if (idx < 49152) {
        int j = idx - 32768; int n = j >> 7, k = j & 127;
        w = w_op[k * 128 + n];
        H = g_w4h; L = g_w4l; off = j;
    } else {
        int j = idx - 49152; int n = j >> 7, k = j & 127;
        w = (n < 128) ? w_vp[k * 128 + n] : ((n < 155) ? w_om[k * 32 + (n - 128)] : 0.f);
        H = g_w2h; L = g_w2l; off = j;
    }
    __nv_bfloat16 h = __float2bfloat16(w);
    H[off] = h;
    L[off] = __float2bfloat16(w - __bfloat162float(h));
}

__global__ void prep_bias(const float* __restrict__ bn1_g, const float* __restrict__ bn1_b,
                          const float* __restrict__ bn1_m, const float* __restrict__ bn1_v,
                          const float* __restrict__ bn2_g, const float* __restrict__ bn2_b,
                          const float* __restrict__ bn2_m, const float* __restrict__ bn2_v,
                          const float* __restrict__ w_pw0, const float* __restrict__ w_pw1,
                          const float* __restrict__ b_vp,  const float* __restrict__ b_om)
{
    int t = threadIdx.x;
    if (t < 128) {
        float s = 0.f;
        for (int c = 0; c < 128; ++c) {
            float sc = bn1_g[c] * rsqrtf(bn1_v[c] + EPS);
            s += w_pw0[t * 128 + c] * (bn1_b[c] - bn1_m[c] * sc);
        }
        g_bias0[t] = s;
        float s2 = 0.f;
        for (int c = 0; c < 128; ++c) {
            float sc = bn2_g[c] * rsqrtf(bn2_v[c] + EPS);
            s2 += w_pw1[t * 128 + c] * (bn2_b[c] - bn2_m[c] * sc);
        }
        g_bias1[t] = s2;
    }
    if (t < 192) {
        g_bcat[t] = (t < 128) ? b_vp[t] : ((t < 155) ? b_om[t - 128] : 0.f);
        g_zero[t] = 0.f;
    }
}

// ---------------------------------------------------------------------------
// Transpose-convert: per batch view [128 k][4096 s] -> token-major bf16 hi/lo
// ---------------------------------------------------------------------------
__global__ void __launch_bounds__(256, 4)
tconv(const float* __restrict__ in, __nv_bfloat16* __restrict__ oh, __nv_bfloat16* __restrict__ ol)
{
    __shared__ float tile[32][129];
    int b = blockIdx.z, k0 = blockIdx.y * 32, s0 = blockIdx.x * 128;
    const float* src = in + (size_t)b * 524288 + (size_t)k0 * 4096 + s0;
    for (int i = threadIdx.x; i < 1024; i += 256) {
        int kk = i >> 5, s4 = (i & 31) << 2;
        float4 v = *(const float4*)(src + (size_t)kk * 4096 + s4);
        tile[kk][s4] = v.x; tile[kk][s4 + 1] = v.y; tile[kk][s4 + 2] = v.z; tile[kk][s4 + 3] = v.w;
    }
    __syncthreads();
    for (int i = threadIdx.x; i < 1024; i += 256) {
        int s = i >> 3, q = i & 7, k = q << 2;
        float v0 = tile[k][s], v1 = tile[k + 1][s], v2 = tile[k + 2][s], v3 = tile[k + 3][s];
        uint2 hq, lq; float l0, l1, l2, l3;
        hq.x = pksplit(v0, v1, l0, l1); hq.y = pksplit(v2, v3, l2, l3);
        lq.x = pk(l0, l1);              lq.y = pk(l2, l3);
        size_t row = (size_t)b * 4096 + s0 + s;
        ((uint2*)(oh + row * 128 + k0))[q] = hq;
        ((uint2*)(ol + row * 128 + k0))[q] = lq;
    }
}

// ---------------------------------------------------------------------------
// Persistent chunk-loop HMMA GEMM with REGISTER-RESIDENT B fragments.
// bf16x3 split (AhBh + AhBl + AlBh), fp32 acc. 32-token chunks, 8 warps
// (2m x 4n). B-hi frags always in registers; B-lo in regs iff BLREG
// (N=128), else re-ldsm'd per chunk (N=192).
// MODE 0: fp32 row-major direct register stores (ldo)
// MODE 1: bf16 hi/lo raw-reshape scatter into step-2 A layout (smem stage)
// MODE 2: fp32 NCHW final output (smem stage)
// ---------------------------------------------------------------------------
template<int N, int MODE, bool BLREG>
__global__ void __launch_bounds__(256, 1)
gemm_mma(const __nv_bfloat16* __restrict__ Ah, const __nv_bfloat16* __restrict__ Al,
         const __nv_bfloat16* __restrict__ Bh, const __nv_bfloat16* __restrict__ Bl,
         const float* __restrict__ biasj,
         float* __restrict__ outF, int ldo,
         __nv_bfloat16* __restrict__ outH, __nv_bfloat16* __restrict__ outL)
{
    constexpr int NW = N / 4;        // per-warp n width
    constexpr int NT = NW / 8;       // 8-col n-tiles per warp
    constexpr int NP = NW / 16;      // ldmatrix n-pairs per warp
    constexpr int BOFF = 2 * N * 256;
    constexpr int ldp = N + 1;

    extern __shared__ char sm[];
    const uint32_t uSM = smem_u32(sm);
    const uint32_t uBh = uSM, uBl = uSM + N * 256;
    float* stage = (float*)(sm + BOFF + 32768);

    const int t = threadIdx.x, w = t >> 5, l = t & 31;
    const int wm = w & 1, wn = w >> 1;
    const int nb0 = wn * NW;

    // hoist bias
    const int cbase = (l & 3) * 2;
    float bj0[NT], bj1[NT];
#pragma unroll
    for (int nt = 0; nt < NT; nt++) {
        int col = nb0 + nt * 8 + cbase;
        bj0[nt] = biasj[col];
        bj1[nt] = biasj[col + 1];
    }

    // B load (once) -> group 0
    {
        const uint4* sh_ = (const uint4*)Bh;
        const uint4* sl_ = (const uint4*)Bl;
        for (int i = t; i < N * 16; i += 256) {
            int r = i >> 4, c = i & 15;
            uint32_t o = tile_off(r, c);
            cpa16(uBh + o, sh_ + i);
            cpa16(uBl + o, sl_ + i);
        }
    }
    cpa_commit();
    int cid = blockIdx.x;
    load_chunkA(uSM + BOFF, Ah, Al, (size_t)cid * CH, t);
    cpa_commit();

    const int arow0 = wm * 16 + (l & 15);
    const int akhalf = l >> 4;
    const int brow_off = (l & 7) + ((l & 16) >> 1);
    const int bkhalf = (l >> 3) & 1;

    // Wait for B (A0 may still be in flight), preload B fragments to regs.
    cpa_wait1();
    __syncthreads();

    uint32_t bhr[8][NP][4];
    uint32_t blr[BLREG ? 8 : 1][NP][4];
#pragma unroll
    for (int ks = 0; ks < 8; ks++) {
#pragma unroll
        for (int np = 0; np < NP; np++) {
            uint32_t off = tile_off(nb0 + np * 16 + brow_off, 2 * ks + bkhalf);
            ldsm4(bhr[ks][np], uBh + off);
            if constexpr (BLREG) ldsm4(blr[ks][np], uBl + off);
        }
    }

    int p = 0;
    while (cid < CHUNKS) {
        const int nxt = cid + (int)gridDim.x;
        const bool hasnext = nxt < CHUNKS;
        if (hasnext) {
            load_chunkA(uSM + BOFF + (p ^ 1) * 16384, Ah, Al, (size_t)nxt * CH, t);
            cpa_commit();
            cpa_wait1();
        } else {
            cpa_wait0();
        }
        __syncthreads();

        const uint32_t uAh = uSM + BOFF + p * 16384;
        const uint32_t uAl = uAh + 8192;

        float d[NT][4];
#pragma unroll
        for (int nt = 0; nt < NT; nt++)
#pragma unroll
            for (int i = 0; i < 4; i++) d[nt][i] = 0.f;

#pragma unroll
        for (int ks = 0; ks < 8; ks++) {
            uint32_t ah[4], al[4];
            {
                uint32_t off = tile_off(arow0, 2 * ks + akhalf);
                ldsm4(ah, uAh + off);
                ldsm4(al, uAl + off);
            }
            // pass 1: Ah*Bh (register B)
#pragma unroll
            for (int np = 0; np < NP; np++) {
                mma16816(d[2 * np],     ah, bhr[ks][np][0], bhr[ks][np][1]);
                mma16816(d[2 * np + 1], ah, bhr[ks][np][2], bhr[ks][np][3]);
            }
            // pass 2: Ah*Bl
            if constexpr (BLREG) {
#pragma unroll
                for (int np = 0; np < NP; np++) {
                    mma16816(d[2 * np],     ah, blr[ks][np][0], blr[ks][np][1]);
                    mma16816(d[2 * np + 1], ah, blr[ks][np][2], blr[ks][np][3]);
                }
            } else {
#pragma unroll
                for (int np = 0; np < NP; np++) {
                    uint32_t bl[4];
                    ldsm4(bl, uBl + tile_off(nb0 + np * 16 + brow_off, 2 * ks + bkhalf));
                    mma16816(d[2 * np],     ah, bl[0], bl[1]);
                    mma16816(d[2 * np + 1], ah, bl[2], bl[3]);
                }
            }
            // pass 3: Al*Bh
#pragma unroll
            for (int np = 0; np < NP; np++) {
                mma16816(d[2 * np],     al, bhr[ks][np][0], bhr[ks][np][1]);
                mma16816(d[2 * np + 1], al, bhr[ks][np][2], bhr[ks][np][3]);
            }
        }

        const size_t m0 = (size_t)cid * CH;
        const int rbase = wm * 16 + (l >> 2);

        if (MODE == 0) {
#pragma unroll
            for (int nt = 0; nt < NT; nt++) {
                int col = nb0 + nt * 8 + cbase;
                float2 v0 = make_float2(d[nt][0] + bj0[nt], d[nt][1] + bj1[nt]);
                float2 v1 = make_float2(d[nt][2] + bj0[nt], d[nt][3] + bj1[nt]);
                *(float2*)(outF + (m0 + rbase) * (size_t)ldo + col) = v0;
                *(float2*)(outF + (m0 + rbase + 8) * (size_t)ldo + col) = v1;
            }
        } else {
#pragma unroll
            for (int nt = 0; nt < NT; nt++) {
                int col = nb0 + nt * 8 + cbase;
                stage[rbase * ldp + col]           = d[nt][0] + bj0[nt];
                stage[rbase * ldp + col + 1]       = d[nt][1] + bj1[nt];
                stage[(rbase + 8) * ldp + col]     = d[nt][2] + bj0[nt];
                stage[(rbase + 8) * ldp + col + 1] = d[nt][3] + bj1[nt];
            }
            __syncthreads();
            if (MODE == 1) {
                // scatter: D[(b,s)][n] -> A2[b*4096 + n*32 + s>>7][s&127]
                const int b  = (int)(m0 >> 12);
                const int sh = (int)((m0 & 4095) >> 7);
                const int cb = (int)(m0 & 96);
                for (int i = t; i < N * 8; i += 256) {
                    int n = i >> 3, q = i & 7, j0 = q * 4;
                    float v0 = stage[(j0 + 0) * ldp + n], v1 = stage[(j0 + 1) * ldp + n];
                    float v2 = stage[(j0 + 2) * ldp + n], v3 = stage[(j0 + 3) * ldp + n];
                    uint2 hq, lq; float r0, r1, r2, r3;
                    hq.x = pksplit(v0, v1, r0, r1); hq.y = pksplit(v2, v3, r2, r3);
                    lq.x = pk(r0, r1);              lq.y = pk(r2, r3);
                    size_t row = (size_t)b * 4096 + (size_t)n * 32 + sh;
                    ((uint2*)(outH + row * 128 + cb))[q] = hq;
                    ((uint2*)(outL + row * 128 + cb))[q] = lq;
                }
            } else {
                // NCHW: D[(b, s0+j)][n] -> out[b][n][s0+j]
                const int b  = (int)(m0 >> 12);
                const int s0 = (int)(m0 & 4095);
                for (int i = t; i < N * 8; i += 256) {
                    int n = i >> 3, q = i & 7, j0 = q * 4;
                    float4 v = make_float4(stage[(j0 + 0) * ldp + n], stage[(j0 + 1) * ldp + n],
                                           stage[(j0 + 2) * ldp + n], stage[(j0 + 3) * ldp + n]);
                    *(float4*)(outF + (size_t)b * 524288 + (size_t)n * 4096 + s0 + j0) = v;
                }
            }
        }
        __syncthreads();   // protect A buffer / stage before next iteration
        p ^= 1;
        cid = nxt;
    }
}

// ---------------------------------------------------------------------------
// DCNv4 core (fp32) -> bf16 hi/lo output
// ---------------------------------------------------------------------------
__global__ void dcn_kernel(const float* __restrict__ vpom,
                           __nv_bfloat16* __restrict__ oh, __nv_bfloat16* __restrict__ ol)
{
    const int warp = threadIdx.x >> 5;
    const int lane = threadIdx.x & 31;
    const int pos  = blockIdx.x * 8 + warp;
    const int b = pos >> 12;
    const int s = pos & 4095;
    const int h = s >> 6;
    const int w = s & 63;

    const float* omp = vpom + (size_t)pos * 192 + 128;
    float omv = (lane < 27) ? omp[lane] : 0.f;

    const float* vb = vpom + ((size_t)b << 12) * 192;
    const int coff = lane << 2;

    float4 acc = make_float4(0.f, 0.f, 0.f, 0.f);

#pragma unroll
    for (int k = 0; k < 9; ++k) {
        float dx = __shfl_sync(0xffffffffu, omv, 3 * k);
        float dy = __shfl_sync(0xffffffffu, omv, 3 * k + 1);
        float m  = __shfl_sync(0xffffffffu, omv, 3 * k + 2);
        float px = (float)(w + (k % 3) - 1) + dx;
        float py = (float)(h + (k / 3) - 1) + dy;
        float xf = floorf(px), yf = floorf(py);
        float fx = px - xf,    fy = py - yf;
        int x0 = (int)xf, y0 = (int)yf;
#pragma unroll
        for (int cy = 0; cy < 2; ++cy) {
#pragma unroll
            for (int cx = 0; cx < 2; ++cx) {
                int xi = x0 + cx, yi = y0 + cy;
                float wt = (cx ? fx : 1.f - fx) * (cy ? fy : 1.f - fy) * m;
                if (xi < 0 || xi > 63 || yi < 0 || yi > 63) wt = 0.f;
                int xc = min(max(xi, 0), 63);
                int yc = min(max(yi, 0), 63);
                const float4 v = *(const float4*)(vb + (size_t)(yc * 64 + xc) * 192 + coff);
                acc.x += wt * v.x; acc.y += wt * v.y;
                acc.z += wt * v.z; acc.w += wt * v.w;
            }
        }
    }
    uint2 hq, lq; float l0, l1, l2, l3;
    hq.x = pksplit(acc.x, acc.y, l0, l1); hq.y = pksplit(acc.z, acc.w, l2, l3);
    lq.x = pk(l0, l1);                    lq.y = pk(l2, l3);
    *(uint2*)(oh + (size_t)pos * 128 + coff) = hq;
    *(uint2*)(ol + (size_t)pos * 128 + coff) = lq;
}

// ---------------------------------------------------------------------------
// Launcher
// ---------------------------------------------------------------------------
extern "C" void kernel_launch(void* const* d_in, const int* in_sizes, int n_in,
                              void* d_out, int out_size)
{
    (void)in_sizes; (void)n_in; (void)out_size;
    const float* x     = (const float*)d_in[0];
    const float* bn1_g = (const float*)d_in[1];
    const float* bn1_b = (const float*)d_in[2];
    const float* bn1_m = (const float*)d_in[3];
    const float* bn1_v = (const float*)d_in[4];
    const float* w_pw0 = (const float*)d_in[5];
    const float* w_vp  = (const float*)d_in[6];
    const float* b_vp  = (const float*)d_in[7];
    const float* w_om  = (const float*)d_in[8];
    const float* b_om  = (const float*)d_in[9];
    const float* w_op  = (const float*)d_in[10];
    const float* bn2_g = (const float*)d_in[11];
    const float* bn2_b = (const float*)d_in[12];
    const float* bn2_m = (const float*)d_in[13];
    const float* bn2_v = (const float*)d_in[14];
    const float* w_pw1 = (const float*)d_in[15];
    float* out = (float*)d_out;

    __nv_bfloat16 *xth, *xtl, *a2h, *a2l, *dch, *dcl, *oth, *otl;
    __nv_bfloat16 *w1h, *w1l, *w2h, *w2l, *w4h, *w4l, *w5h, *w5l;
    float *vpom, *op, *bias0, *bias1, *bcat, *zero;
    cudaGetSymbolAddress((void**)&xth, g_xt_hi);  cudaGetSymbolAddress((void**)&xtl, g_xt_lo);
    cudaGetSymbolAddress((void**)&a2h, g_a2_hi);  cudaGetSymbolAddress((void**)&a2l, g_a2_lo);
    cudaGetSymbolAddress((void**)&dch, g_dcn_hi); cudaGetSymbolAddress((void**)&dcl, g_dcn_lo);
    cudaGetSymbolAddress((void**)&oth, g_ot_hi);  cudaGetSymbolAddress((void**)&otl, g_ot_lo);
    cudaGetSymbolAddress((void**)&w1h, g_w1h);    cudaGetSymbolAddress((void**)&w1l, g_w1l);
    cudaGetSymbolAddress((void**)&w2h, g_w2h);    cudaGetSymbolAddress((void**)&w2l, g_w2l);
    cudaGetSymbolAddress((void**)&w4h, g_w4h);    cudaGetSymbolAddress((void**)&w4l, g_w4l);
    cudaGetSymbolAddress((void**)&w5h, g_w5h);    cudaGetSymbolAddress((void**)&w5l, g_w5l);
    cudaGetSymbolAddress((void**)&vpom, g_vpom);  cudaGetSymbolAddress((void**)&op, g_op);
    cudaGetSymbolAddress((void**)&bias0, g_bias0); cudaGetSymbolAddress((void**)&bias1, g_bias1);
    cudaGetSymbolAddress((void**)&bcat, g_bcat);  cudaGetSymbolAddress((void**)&zero, g_zero);

    // smem: B(2*N*256) + A dbuf(32768) + stage(32*(N+1)*4)
    const int SM128 = 2 * 128 * 256 + 32768 + 32 * 129 * 4;   // 114816
    const int SM192 = 2 * 192 * 256 + 32768 + 32 * 193 * 4;   // 155776
    cudaFuncSetAttribute((const void*)gemm_mma<128, 0, true>,  cudaFuncAttributeMaxDynamicSharedMemorySize, SM128);
    cudaFuncSetAttribute((const void*)gemm_mma<128, 1, true>,  cudaFuncAttributeMaxDynamicSharedMemorySize, SM128);
    cudaFuncSetAttribute((const void*)gemm_mma<128, 2, true>,  cudaFuncAttributeMaxDynamicSharedMemorySize, SM128);
    cudaFuncSetAttribute((const void*)gemm_mma<192, 0, false>, cudaFuncAttributeMaxDynamicSharedMemorySize, SM192);

    const int GRID = 148;   // 1 persistent CTA per SM (registers hold B frags)

    prep_weights<<<288, 256>>>(w_pw0, w_pw1, w_vp, w_om, w_op, bn1_g, bn1_v, bn2_g, bn2_v);
    prep_bias<<<1, 256>>>(bn1_g, bn1_b, bn1_m, bn1_v, bn2_g, bn2_b, bn2_m, bn2_v,
                          w_pw0, w_pw1, b_vp, b_om);

    // 1) x (NCHW) -> token-major hi/lo; x1 = x @ w1^T + bias0 scattered into
    //    step-2's raw-reshape A layout.
    tconv<<<dim3(32, 4, 8), 256>>>(x, xth, xtl);
    gemm_mma<128, 1, true><<<GRID, 256, SM128>>>(xth, xtl, w1h, w1l, bias0, nullptr, 0, a2h, a2l);

    // 2) vpom = x1_view @ [w_vp|w_om]^T + bcat  (fp32, ld 192)
    gemm_mma<192, 0, false><<<GRID, 256, SM192>>>(a2h, a2l, w2h, w2l, bcat, vpom, 192, nullptr, nullptr);

    // 3) DCNv4 core -> bf16 hi/lo
    dcn_kernel<<<4096, 256>>>(vpom, dch, dcl);

    // 4) op = dcn @ w_op  (fp32 token-major = NCHW raw view)
    gemm_mma<128, 0, true><<<GRID, 256, SM128>>>(dch, dcl, w4h, w4l, zero, op, 128, nullptr, nullptr);

    // 5) out = (BN2-folded pw1) on NCHW view of op
    tconv<<<dim3(32, 4, 8), 256>>>(op, oth, otl);
    gemm_mma<128, 2, true><<<GRID, 256, SM128>>>(oth, otl, w5h, w5l, bias1, out, 0, nullptr, nullptr);
}

// round 8
// speedup vs baseline: 1.0337x; 1.0337x over previous
#include <cuda_runtime.h>
#include <cuda_bf16.h>
#include <cstdint>
#include <math.h>

#define DI __device__ __forceinline__

constexpr int TOK = 32768;           // 8 * 64 * 64
constexpr float EPS = 1e-5f;
constexpr int CH = 64;               // tokens per chunk
constexpr int CHUNKS = TOK / CH;     // 512

// ---------------------------------------------------------------------------
// Device scratch
// ---------------------------------------------------------------------------
__device__ __align__(16) __nv_bfloat16 g_a2_hi[TOK * 128], g_a2_lo[TOK * 128];
__device__ __align__(16) float         g_vpom[TOK * 192];
__device__ __align__(16) __nv_bfloat16 g_dcn_hi[TOK * 128], g_dcn_lo[TOK * 128];
__device__ __align__(16) float         g_op[TOK * 128];

__device__ __align__(16) __nv_bfloat16 g_w1h[128 * 128], g_w1l[128 * 128];
__device__ __align__(16) __nv_bfloat16 g_w2h[192 * 128], g_w2l[192 * 128];
__device__ __align__(16) __nv_bfloat16 g_w4h[128 * 128], g_w4l[128 * 128];
__device__ __align__(16) __nv_bfloat16 g_w5h[128 * 128], g_w5l[128 * 128];
__device__ float g_bias0[128], g_bias1[128], g_bcat[192], g_zero[192];

// ---------------------------------------------------------------------------
// Helpers
// ---------------------------------------------------------------------------
DI uint32_t smem_u32(const void* p) {
    uint32_t a;
    asm("{ .reg .u64 t; cvta.to.shared.u64 t, %1; cvt.u32.u64 %0, t; }" : "=r"(a) : "l"(p));
    return a;
}

DI void cpa16(uint32_t dst, const void* src) {
    asm volatile("{ .reg .u64 g; cvta.to.global.u64 g, %1; "
                 "cp.async.cg.shared.global [%0], [g], 16; }"
                 :: "r"(dst), "l"(src));
}
DI void cpa_commit() { asm volatile("cp.async.commit_group;" ::: "memory"); }
DI void cpa_wait0() { asm volatile("cp.async.wait_group 0;" ::: "memory"); }
DI void cpa_wait1() { asm volatile("cp.async.wait_group 1;" ::: "memory"); }

DI void ldsm4(uint32_t (&r)[4], uint32_t addr) {
    asm volatile("ldmatrix.sync.aligned.m8n8.x4.shared.b16 {%0,%1,%2,%3}, [%4];"
                 : "=r"(r[0]), "=r"(r[1]), "=r"(r[2]), "=r"(r[3]) : "r"(addr));
}

DI void mma16816(float (&d)[4], const uint32_t (&a)[4], uint32_t b0, uint32_t b1) {
    asm volatile("mma.sync.aligned.m16n8k16.row.col.f32.bf16.bf16.f32 "
                 "{%0,%1,%2,%3}, {%4,%5,%6,%7}, {%8,%9}, {%0,%1,%2,%3};"
                 : "+f"(d[0]), "+f"(d[1]), "+f"(d[2]), "+f"(d[3])
                 : "r"(a[0]), "r"(a[1]), "r"(a[2]), "r"(a[3]), "r"(b0), "r"(b1));
}

// XOR-swizzled bf16 tile: row stride 256 B (128 bf16), 16B chunk c -> c ^ (row&7)
DI uint32_t tile_off(int r, int chunk) { return (uint32_t)(r * 256 + ((chunk ^ (r & 7)) << 4)); }

DI uint32_t pk(float a, float b) {
    __nv_bfloat16 ha = __float2bfloat16(a), hb = __float2bfloat16(b);
    return ((uint32_t)__bfloat16_as_ushort(hb) << 16) | (uint32_t)__bfloat16_as_ushort(ha);
}
DI uint32_t pksplit(float a, float b, float& ra, float& rb) {
    __nv_bfloat16 ha = __float2bfloat16(a), hb = __float2bfloat16(b);
    ra = a - __bfloat162float(ha);
    rb = b - __bfloat162float(hb);
    return ((uint32_t)__bfloat16_as_ushort(hb) << 16) | (uint32_t)__bfloat16_as_ushort(ha);
}

// fp32 pair -> bf16x2 hi fragment + bf16x2 lo fragment (exact residual split)
DI void splitpair(float f0, float f1, uint32_t& hi, uint32_t& lo) {
    uint32_t h;
    asm("cvt.rn.bf16x2.f32 %0, %1, %2;" : "=r"(h) : "f"(f1), "f"(f0));  // high<-f1, low<-f0
    float h0 = __uint_as_float(h << 16);
    float h1 = __uint_as_float(h & 0xFFFF0000u);
    float l0 = f0 - h0, l1 = f1 - h1;
    asm("cvt.rn.bf16x2.f32 %0, %1, %2;" : "=r"(lo) : "f"(l1), "f"(l0));
    hi = h;
}

// ---------------------------------------------------------------------------
// Weight prep: fold BN, transpose to [n][k], split bf16 hi/lo
// ---------------------------------------------------------------------------
__global__ void prep_weights(const float* __restrict__ w_pw0, const float* __restrict__ w_pw1,
                             const float* __restrict__ w_vp,  const float* __restrict__ w_om,
                             const float* __restrict__ w_op,
                             const float* __restrict__ bn1_g, const float* __restrict__ bn1_v,
                             const float* __restrict__ bn2_g, const float* __restrict__ bn2_v)
{
    int idx = blockIdx.x * blockDim.x + threadIdx.x;
    if (idx >= 73728) return;
    float w; __nv_bfloat16 *H, *L; int off;
    if (idx < 16384) {
        int k = idx & 127;
        w = w_pw0[idx] * bn1_g[k] * rsqrtf(bn1_v[k] + EPS);
        H = g_w1h; L = g_w1l; off = idx;
    } else if (idx < 32768) {
        int j = idx - 16384; int k = j & 127;
        w = w_pw1[j] * bn2_g[k] * rsqrtf(bn2_v[k] + EPS);
        H = g_w5h; L = g_w5l; off = j;
    } else if (idx < 49152) {
        int j = idx - 32768; int n = j >> 7, k = j & 127;
        w = w_op[k * 128 + n];
        H = g_w4h; L = g_w4l; off = j;
    } else {
        int j = idx - 49152; int n = j >> 7, k = j & 127;
        w = (n < 128) ? w_vp[k * 128 + n] : ((n < 155) ? w_om[k * 32 + (n - 128)] : 0.f);
        H = g_w2h; L = g_w2l; off = j;
    }
    __nv_bfloat16 h = __float2bfloat16(w);
    H[off] = h;
    L[off] = __float2bfloat16(w - __bfloat162float(h));
}

__global__ void prep_bias(const float* __restrict__ bn1_g, const float* __restrict__ bn1_b,
                          const float* __restrict__ bn1_m, const float* __restrict__ bn1_v,
                          const float* __restrict__ bn2_g, const float* __restrict__ bn2_b,
                          const float* __restrict__ bn2_m, const float* __restrict__ bn2_v,
                          const float* __restrict__ w_pw0, const float* __restrict__ w_pw1,
                          const float* __restrict__ b_vp,  const float* __restrict__ b_om)
{
    int t = threadIdx.x;
    if (t < 128) {
        float s = 0.f;
        for (int c = 0; c < 128; ++c) {
            float sc = bn1_g[c] * rsqrtf(bn1_v[c] + EPS);
            s += w_pw0[t * 128 + c] * (bn1_b[c] - bn1_m[c] * sc);
        }
        g_bias0[t] = s;
        float s2 = 0.f;
        for (int c = 0; c < 128; ++c) {
            float sc = bn2_g[c] * rsqrtf(bn2_v[c] + EPS);
            s2 += w_pw1[t * 128 + c] * (bn2_b[c] - bn2_m[c] * sc);
        }
        g_bias1[t] = s2;
    }
    if (t < 192) {
        g_bcat[t] = (t < 128) ? b_vp[t] : ((t < 155) ? b_om[t - 128] : 0.f);
        g_zero[t] = 0.f;
    }
}

// ---------------------------------------------------------------------------
// Persistent chunk-loop HMMA GEMM. bf16x3 split (AhBh + AhBl + AlBh), fp32 acc.
// 64-token chunks; 8 warps = 2m(32) x 4n(N/4); warp m-tile 32 (mt=2).
// A path:
//   AKM=false: A pre-split bf16 hi/lo token-major (ldsm)
//   AKM=true : A fp32 k-major NCHW view (Af + b*524288 + k*4096 + s); chunk
//              staged in smem fp32, fragments built via LDS + bf16x2 split.
// MODE 0: fp32 row-major direct register stores (ldo)
// MODE 1: bf16 hi/lo raw-reshape scatter into step-2 A layout (smem stage)
// MODE 2: fp32 NCHW final output (smem stage)
// ---------------------------------------------------------------------------
template<int N, int MODE, bool AKM>
__global__ void __launch_bounds__(256, 1)
gemm_mma(const float* __restrict__ Af,
         const __nv_bfloat16* __restrict__ Ah, const __nv_bfloat16* __restrict__ Al,
         const __nv_bfloat16* __restrict__ Bh, const __nv_bfloat16* __restrict__ Bl,
         const float* __restrict__ biasj,
         float* __restrict__ outF, int ldo,
         __nv_bfloat16* __restrict__ outH, __nv_bfloat16* __restrict__ outL)
{
    constexpr int NW = N / 4;        // per-warp n width
    constexpr int NT = NW / 8;       // 8-col n-tiles per warp
    constexpr int NP = NW / 16;      // ldmatrix n-pairs per warp
    constexpr int BOFF = 2 * N * 256;
    constexpr int ABUF = AKM ? (128 * 272) : (2 * CH * 256);   // per-stage bytes
    constexpr int ldp = N + 1;

    extern __shared__ char sm[];
    const uint32_t uSM = smem_u32(sm);
    const uint32_t uBh = uSM, uBl = uSM + N * 256;
    float* stage = (float*)(sm + BOFF + 2 * ABUF);

    const int t = threadIdx.x, w = t >> 5, l = t & 31;
    const int wm = w & 1, wn = w >> 1;
    const int nb0 = wn * NW;

    // hoist bias
    const int cbase = (l & 3) * 2;
    float bj0[NT], bj1[NT];
#pragma unroll
    for (int nt = 0; nt < NT; nt++) {
        int col = nb0 + nt * 8 + cbase;
        bj0[nt] = biasj[col];
        bj1[nt] = biasj[col + 1];
    }

    // B load (once)
    {
        const uint4* sh_ = (const uint4*)Bh;
        const uint4* sl_ = (const uint4*)Bl;
        for (int i = t; i < N * 16; i += 256) {
            int r = i >> 4, c = i & 15;
            uint32_t o = tile_off(r, c);
            cpa16(uBh + o, sh_ + i);
            cpa16(uBl + o, sl_ + i);
        }
    }
    cpa_commit();

    // A chunk loader
    auto loadA = [&](uint32_t dst, int cid_) {
        size_t m0 = (size_t)cid_ * CH;
        if constexpr (AKM) {
            const float* base = Af + (m0 >> 12) * 524288 + (m0 & 4095);
            for (int i = t; i < 2048; i += 256) {
                int k = i >> 4, u = i & 15;
                cpa16(dst + (uint32_t)(k * 272 + u * 16), base + (size_t)k * 4096 + u * 4);
            }
        } else {
            const uint4* sh_ = (const uint4*)(Ah + m0 * 128);
            const uint4* sl_ = (const uint4*)(Al + m0 * 128);
            for (int i = t; i < 1024; i += 256) {
                int r = i >> 4, c = i & 15;
                uint32_t o = tile_off(r, c);
                cpa16(dst + o, sh_ + i);
                cpa16(dst + 16384 + o, sl_ + i);
            }
        }
    };

    int cid = blockIdx.x;
    loadA(uSM + BOFF, cid);
    cpa_commit();

    const int arow_lo = wm * 32 + (l & 15);      // !AKM ldsm row base (mt adds 16)
    const int akhalf = l >> 4;
    const int brow_off = (l & 7) + ((l & 16) >> 1);
    const int bkhalf = (l >> 3) & 1;
    const int mfrag = wm * 32 + (l >> 2);        // AKM fragment column base
    const int kfrag = (l & 3) * 2;               // AKM fragment k base within k16 group

    int p = 0;
    while (cid < CHUNKS) {
        const int nxt = cid + (int)gridDim.x;
        const bool hasnext = nxt < CHUNKS;
        if (hasnext) {
            loadA(uSM + BOFF + (p ^ 1) * ABUF, nxt);
            cpa_commit();
            cpa_wait1();
        } else {
            cpa_wait0();
        }
        __syncthreads();

        const uint32_t uA = uSM + BOFF + p * ABUF;
        const float* tileA = (const float*)(sm + BOFF + p * ABUF);   // AKM view

        float d[2][NT][4];
#pragma unroll
        for (int mt = 0; mt < 2; mt++)
#pragma unroll
            for (int nt = 0; nt < NT; nt++)
#pragma unroll
                for (int i = 0; i < 4; i++) d[mt][nt][i] = 0.f;

#pragma unroll
        for (int ks = 0; ks < 8; ks++) {
            uint32_t ah[2][4], al[2][4];
            if constexpr (AKM) {
#pragma unroll
                for (int mt = 0; mt < 2; mt++) {
                    int mlo = mfrag + mt * 16;
                    int k0 = ks * 16 + kfrag;
                    // a0: (mlo, k0..k0+1)  a1: (mlo+8, k0..)  a2: (mlo, k0+8..)  a3: (mlo+8, k0+8..)
                    float f;
                    float g0 = tileA[(k0    ) * 68 + mlo];
                    f        = tileA[(k0 + 1) * 68 + mlo];
                    splitpair(g0, f, ah[mt][0], al[mt][0]);
                    g0 = tileA[(k0    ) * 68 + mlo + 8];
                    f  = tileA[(k0 + 1) * 68 + mlo + 8];
                    splitpair(g0, f, ah[mt][1], al[mt][1]);
                    g0 = tileA[(k0 + 8) * 68 + mlo];
                    f  = tileA[(k0 + 9) * 68 + mlo];
                    splitpair(g0, f, ah[mt][2], al[mt][2]);
                    g0 = tileA[(k0 + 8) * 68 + mlo + 8];
                    f  = tileA[(k0 + 9) * 68 + mlo + 8];
                    splitpair(g0, f, ah[mt][3], al[mt][3]);
                }
            } else {
#pragma unroll
                for (int mt = 0; mt < 2; mt++) {
                    uint32_t off = tile_off(arow_lo + mt * 16, 2 * ks + akhalf);
                    ldsm4(ah[mt], uA + off);
                    ldsm4(al[mt], uA + 16384 + off);
                }
            }
            uint32_t bh[NP][4], bl[NP][4];
#pragma unroll
            for (int np = 0; np < NP; np++) {
                uint32_t off = tile_off(nb0 + np * 16 + brow_off, 2 * ks + bkhalf);
                ldsm4(bh[np], uBh + off);
                ldsm4(bl[np], uBl + off);
            }
            // pass 1: Ah*Bh  (8 independent MMAs before any accumulator reuse)
#pragma unroll
            for (int np = 0; np < NP; np++)
#pragma unroll
                for (int mt = 0; mt < 2; mt++) {
                    mma16816(d[mt][2 * np],     ah[mt], bh[np][0], bh[np][1]);
                    mma16816(d[mt][2 * np + 1], ah[mt], bh[np][2], bh[np][3]);
                }
            // pass 2: Ah*Bl
#pragma unroll
            for (int np = 0; np < NP; np++)
#pragma unroll
                for (int mt = 0; mt < 2; mt++) {
                    mma16816(d[mt][2 * np],     ah[mt], bl[np][0], bl[np][1]);
                    mma16816(d[mt][2 * np + 1], ah[mt], bl[np][2], bl[np][3]);
                }
            // pass 3: Al*Bh
#pragma unroll
            for (int np = 0; np < NP; np++)
#pragma unroll
                for (int mt = 0; mt < 2; mt++) {
                    mma16816(d[mt][2 * np],     al[mt], bh[np][0], bh[np][1]);
                    mma16816(d[mt][2 * np + 1], al[mt], bh[np][2], bh[np][3]);
                }
        }

        const size_t m0 = (size_t)cid * CH;
        const int rloc = wm * 32 + (l >> 2);

        if (MODE == 0) {
#pragma unroll
            for (int mt = 0; mt < 2; mt++)
#pragma unroll
                for (int nt = 0; nt < NT; nt++) {
                    int row = rloc + mt * 16;
                    int col = nb0 + nt * 8 + cbase;
                    float2 v0 = make_float2(d[mt][nt][0] + bj0[nt], d[mt][nt][1] + bj1[nt]);
                    float2 v1 = make_float2(d[mt][nt][2] + bj0[nt], d[mt][nt][3] + bj1[nt]);
                    *(float2*)(outF + (m0 + row) * (size_t)ldo + col) = v0;
                    *(float2*)(outF + (m0 + row + 8) * (size_t)ldo + col) = v1;
                }
        } else {
#pragma unroll
            for (int mt = 0; mt < 2; mt++)
#pragma unroll
                for (int nt = 0; nt < NT; nt++) {
                    int row = rloc + mt * 16;
                    int col = nb0 + nt * 8 + cbase;
                    stage[row * ldp + col]           = d[mt][nt][0] + bj0[nt];
                    stage[row * ldp + col + 1]       = d[mt][nt][1] + bj1[nt];
                    stage[(row + 8) * ldp + col]     = d[mt][nt][2] + bj0[nt];
                    stage[(row + 8) * ldp + col + 1] = d[mt][nt][3] + bj1[nt];
                }
            __syncthreads();
            if (MODE == 1) {
                // scatter: D[(b,s)][n] -> A2[b*4096 + n*32 + s>>7][s&127]
                const int b  = (int)(m0 >> 12);
                const int sh = (int)((m0 & 4095) >> 7);
                const int cb = (int)(m0 & 64);
                for (int i = t; i < N * 16; i += 256) {
                    int n = i >> 4, q = i & 15, j0 = q * 4;
                    float v0 = stage[(j0 + 0) * ldp + n], v1 = stage[(j0 + 1) * ldp + n];
                    float v2 = stage[(j0 + 2) * ldp + n], v3 = stage[(j0 + 3) * ldp + n];
                    uint2 hq, lq; float r0, r1, r2, r3;
                    hq.x = pksplit(v0, v1, r0, r1); hq.y = pksplit(v2, v3, r2, r3);
                    lq.x = pk(r0, r1);              lq.y = pk(r2, r3);
                    size_t row = (size_t)b * 4096 + (size_t)n * 32 + sh;
                    ((uint2*)(outH + row * 128 + cb))[q] = hq;
                    ((uint2*)(outL + row * 128 + cb))[q] = lq;
                }
            } else {
                // NCHW: D[(b, s0+j)][n] -> out[b][n][s0+j]
                const int b  = (int)(m0 >> 12);
                const int s0 = (int)(m0 & 4095);
                for (int i = t; i < N * 16; i += 256) {
                    int n = i >> 4, q = i & 15, j0 = q * 4;
                    float4 v = make_float4(stage[(j0 + 0) * ldp + n], stage[(j0 + 1) * ldp + n],
                                           stage[(j0 + 2) * ldp + n], stage[(j0 + 3) * ldp + n]);
                    *(float4*)(outF + (size_t)b * 524288 + (size_t)n * 4096 + s0 + j0) = v;
                }
            }
        }
        __syncthreads();   // protect A buffer / stage before next iteration
        p ^= 1;
        cid = nxt;
    }
}

// ---------------------------------------------------------------------------
// DCNv4 core (fp32) -> bf16 hi/lo output
// ---------------------------------------------------------------------------
__global__ void dcn_kernel(const float* __restrict__ vpom,
                           __nv_bfloat16* __restrict__ oh, __nv_bfloat16* __restrict__ ol)
{
    const int warp = threadIdx.x >> 5;
    const int lane = threadIdx.x & 31;
    const int pos  = blockIdx.x * 8 + warp;
    const int b = pos >> 12;
    const int s = pos & 4095;
    const int h = s >> 6;
    const int w = s & 63;

    const float* omp = vpom + (size_t)pos * 192 + 128;
    float omv = (lane < 27) ? omp[lane] : 0.f;

    const float* vb = vpom + ((size_t)b << 12) * 192;
    const int coff = lane << 2;

    float4 acc = make_float4(0.f, 0.f, 0.f, 0.f);

#pragma unroll
    for (int k = 0; k < 9; ++k) {
        float dx = __shfl_sync(0xffffffffu, omv, 3 * k);
        float dy = __shfl_sync(0xffffffffu, omv, 3 * k + 1);
        float m  = __shfl_sync(0xffffffffu, omv, 3 * k + 2);
        float px = (float)(w + (k % 3) - 1) + dx;
        float py = (float)(h + (k / 3) - 1) + dy;
        float xf = floorf(px), yf = floorf(py);
        float fx = px - xf,    fy = py - yf;
        int x0 = (int)xf, y0 = (int)yf;
#pragma unroll
        for (int cy = 0; cy < 2; ++cy) {
#pragma unroll
            for (int cx = 0; cx < 2; ++cx) {
                int xi = x0 + cx, yi = y0 + cy;
                float wt = (cx ? fx : 1.f - fx) * (cy ? fy : 1.f - fy) * m;
                if (xi < 0 || xi > 63 || yi < 0 || yi > 63) wt = 0.f;
                int xc = min(max(xi, 0), 63);
                int yc = min(max(yi, 0), 63);
                const float4 v = *(const float4*)(vb + (size_t)(yc * 64 + xc) * 192 + coff);
                acc.x += wt * v.x; acc.y += wt * v.y;
                acc.z += wt * v.z; acc.w += wt * v.w;
            }
        }
    }
    uint2 hq, lq; float l0, l1, l2, l3;
    hq.x = pksplit(acc.x, acc.y, l0, l1); hq.y = pksplit(acc.z, acc.w, l2, l3);
    lq.x = pk(l0, l1);                    lq.y = pk(l2, l3);
    *(uint2*)(oh + (size_t)pos * 128 + coff) = hq;
    *(uint2*)(ol + (size_t)pos * 128 + coff) = lq;
}

// ---------------------------------------------------------------------------
// Launcher
// ---------------------------------------------------------------------------
extern "C" void kernel_launch(void* const* d_in, const int* in_sizes, int n_in,
                              void* d_out, int out_size)
{
    (void)in_sizes; (void)n_in; (void)out_size;
    const float* x     = (const float*)d_in[0];
    const float* bn1_g = (const float*)d_in[1];
    const float* bn1_b = (const float*)d_in[2];
    const float* bn1_m = (const float*)d_in[3];
    const float* bn1_v = (const float*)d_in[4];
    const float* w_pw0 = (const float*)d_in[5];
    const float* w_vp  = (const float*)d_in[6];
    const float* b_vp  = (const float*)d_in[7];
    const float* w_om  = (const float*)d_in[8];
    const float* b_om  = (const float*)d_in[9];
    const float* w_op  = (const float*)d_in[10];
    const float* bn2_g = (const float*)d_in[11];
    const float* bn2_b = (const float*)d_in[12];
    const float* bn2_m = (const float*)d_in[13];
    const float* bn2_v = (const float*)d_in[14];
    const float* w_pw1 = (const float*)d_in[15];
    float* out = (float*)d_out;

    __nv_bfloat16 *a2h, *a2l, *dch, *dcl;
    __nv_bfloat16 *w1h, *w1l, *w2h, *w2l, *w4h, *w4l, *w5h, *w5l;
    float *vpom, *op, *bias0, *bias1, *bcat, *zero;
    cudaGetSymbolAddress((void**)&a2h, g_a2_hi);  cudaGetSymbolAddress((void**)&a2l, g_a2_lo);
    cudaGetSymbolAddress((void**)&dch, g_dcn_hi); cudaGetSymbolAddress((void**)&dcl, g_dcn_lo);
    cudaGetSymbolAddress((void**)&w1h, g_w1h);    cudaGetSymbolAddress((void**)&w1l, g_w1l);
    cudaGetSymbolAddress((void**)&w2h, g_w2h);    cudaGetSymbolAddress((void**)&w2l, g_w2l);
    cudaGetSymbolAddress((void**)&w4h, g_w4h);    cudaGetSymbolAddress((void**)&w4l, g_w4l);
    cudaGetSymbolAddress((void**)&w5h, g_w5h);    cudaGetSymbolAddress((void**)&w5l, g_w5l);
    cudaGetSymbolAddress((void**)&vpom, g_vpom);  cudaGetSymbolAddress((void**)&op, g_op);
    cudaGetSymbolAddress((void**)&bias0, g_bias0); cudaGetSymbolAddress((void**)&bias1, g_bias1);
    cudaGetSymbolAddress((void**)&bcat, g_bcat);  cudaGetSymbolAddress((void**)&zero, g_zero);

    // smem sizes: B(2*N*256) + A dbuf + stage(64*(N+1)*4 when staged)
    const int SM_AKM1 = 65536 + 2 * 128 * 272 + 64 * 129 * 4;   // 168576 (gemm1/5)
    const int SM_192  = 98304 + 2 * 2 * 64 * 256;               // 163840 (gemm2, MODE0)
    const int SM_128  = 65536 + 2 * 2 * 64 * 256;               // 131072 (gemm4, MODE0)
    cudaFuncSetAttribute((const void*)gemm_mma<128, 1, true>,  cudaFuncAttributeMaxDynamicSharedMemorySize, SM_AKM1);
    cudaFuncSetAttribute((const void*)gemm_mma<128, 2, true>,  cudaFuncAttributeMaxDynamicSharedMemorySize, SM_AKM1);
    cudaFuncSetAttribute((const void*)gemm_mma<192, 0, false>, cudaFuncAttributeMaxDynamicSharedMemorySize, SM_192);
    cudaFuncSetAttribute((const void*)gemm_mma<128, 0, false>, cudaFuncAttributeMaxDynamicSharedMemorySize, SM_128);

    const int GRID = 148;   // 1 persistent CTA per SM

    prep_weights<<<288, 256>>>(w_pw0, w_pw1, w_vp, w_om, w_op, bn1_g, bn1_v, bn2_g, bn2_v);
    prep_bias<<<1, 256>>>(bn1_g, bn1_b, bn1_m, bn1_v, bn2_g, bn2_b, bn2_m, bn2_v,
                          w_pw0, w_pw1, b_vp, b_om);

    // 1) x1 = x(NCHW, read k-major fp32) @ w1^T + bias0, scattered into
    //    step-2's raw-reshape A layout (bf16 hi/lo).
    gemm_mma<128, 1, true><<<GRID, 256, SM_AKM1>>>(x, nullptr, nullptr, w1h, w1l,
                                                   bias0, nullptr, 0, a2h, a2l);

    // 2) vpom = x1_view @ [w_vp|w_om]^T + bcat  (fp32, ld 192)
    gemm_mma<192, 0, false><<<GRID, 256, SM_192>>>(nullptr, a2h, a2l, w2h, w2l,
                                                   bcat, vpom, 192, nullptr, nullptr);

    // 3) DCNv4 core -> bf16 hi/lo
    dcn_kernel<<<4096, 256>>>(vpom, dch, dcl);

    // 4) op = dcn @ w_op  (fp32 token-major = NCHW raw view)
    gemm_mma<128, 0, false><<<GRID, 256, SM_128>>>(nullptr, dch, dcl, w4h, w4l,
                                                   zero, op, 128, nullptr, nullptr);

    // 5) out = (BN2-folded pw1) @ op(NCHW view, read k-major fp32) -> NCHW
    gemm_mma<128, 2, true><<<GRID, 256, SM_AKM1>>>(op, nullptr, nullptr, w5h, w5l,
                                                   bias1, out, 0, nullptr, nullptr);
}

// round 10
// speedup vs baseline: 1.1810x; 1.1426x over previous
#include <cuda_runtime.h>
#include <cuda_bf16.h>
#include <cuda_fp16.h>
#include <cstdint>
#include <math.h>

#define DI __device__ __forceinline__
typedef unsigned short u16;

constexpr int TOK = 32768;           // 8 * 64 * 64
constexpr float EPS = 1e-5f;
constexpr int CH = 64;               // tokens per chunk
constexpr int CHUNKS = TOK / CH;     // 512

// ---------------------------------------------------------------------------
// Device scratch
// ---------------------------------------------------------------------------
__device__ __align__(16) u16   g_a2_hi[TOK * 128], g_a2_lo[TOK * 128]; // bf16 pair
__device__ __align__(16) float g_vpom[TOK * 192];
__device__ __align__(16) u16   g_dcn[TOK * 128];                       // fp16 single
__device__ __align__(16) float g_op[TOK * 128];                        // fp32 token-major

__device__ __align__(16) u16 g_w1h[128 * 128], g_w1l[128 * 128];   // fp16
__device__ __align__(16) u16 g_w2h[192 * 128], g_w2l[192 * 128];   // bf16
__device__ __align__(16) u16 g_w4h[128 * 128], g_w4l[128 * 128];   // fp16
__device__ __align__(16) u16 g_w5h[128 * 128], g_w5l[128 * 128];   // fp16
__device__ float g_bias0[128], g_bias1[128], g_bcat[192], g_zero[192];

// ---------------------------------------------------------------------------
// Helpers
// ---------------------------------------------------------------------------
DI uint32_t smem_u32(const void* p) {
    uint32_t a;
    asm("{ .reg .u64 t; cvta.to.shared.u64 t, %1; cvt.u32.u64 %0, t; }" : "=r"(a) : "l"(p));
    return a;
}

DI void cpa16(uint32_t dst, const void* src) {
    asm volatile("{ .reg .u64 g; cvta.to.global.u64 g, %1; "
                 "cp.async.cg.shared.global [%0], [g], 16; }"
                 :: "r"(dst), "l"(src));
}
DI void cpa_commit() { asm volatile("cp.async.commit_group;" ::: "memory"); }
DI void cpa_wait0() { asm volatile("cp.async.wait_group 0;" ::: "memory"); }
DI void cpa_wait1() { asm volatile("cp.async.wait_group 1;" ::: "memory"); }

DI void ldsm4(uint32_t (&r)[4], uint32_t addr) {
    asm volatile("ldmatrix.sync.aligned.m8n8.x4.shared.b16 {%0,%1,%2,%3}, [%4];"
                 : "=r"(r[0]), "=r"(r[1]), "=r"(r[2]), "=r"(r[3]) : "r"(addr));
}

template<bool F16>
DI void mma_k16(float (&d)[4], const uint32_t (&a)[4], uint32_t b0, uint32_t b1) {
    if constexpr (F16)
        asm volatile("mma.sync.aligned.m16n8k16.row.col.f32.f16.f16.f32 "
                     "{%0,%1,%2,%3}, {%4,%5,%6,%7}, {%8,%9}, {%0,%1,%2,%3};"
                     : "+f"(d[0]), "+f"(d[1]), "+f"(d[2]), "+f"(d[3])
                     : "r"(a[0]), "r"(a[1]), "r"(a[2]), "r"(a[3]), "r"(b0), "r"(b1));
    else
        asm volatile("mma.sync.aligned.m16n8k16.row.col.f32.bf16.bf16.f32 "
                     "{%0,%1,%2,%3}, {%4,%5,%6,%7}, {%8,%9}, {%0,%1,%2,%3};"
                     : "+f"(d[0]), "+f"(d[1]), "+f"(d[2]), "+f"(d[3])
                     : "r"(a[0]), "r"(a[1]), "r"(a[2]), "r"(a[3]), "r"(b0), "r"(b1));
}

// XOR-swizzled 16-bit tile: row stride 256 B (128 elems), 16B chunk c -> c ^ (row&7)
DI uint32_t tile_off(int r, int chunk) { return (uint32_t)(r * 256 + ((chunk ^ (r & 7)) << 4)); }

DI uint32_t pk(float a, float b) {                     // bf16x2 {hi=b, lo=a}
    __nv_bfloat16 ha = __float2bfloat16(a), hb = __float2bfloat16(b);
    return ((uint32_t)__bfloat16_as_ushort(hb) << 16) | (uint32_t)__bfloat16_as_ushort(ha);
}
DI uint32_t pksplit(float a, float b, float& ra, float& rb) {
    __nv_bfloat16 ha = __float2bfloat16(a), hb = __float2bfloat16(b);
    ra = a - __bfloat162float(ha);
    rb = b - __bfloat162float(hb);
    return ((uint32_t)__bfloat16_as_ushort(hb) << 16) | (uint32_t)__bfloat16_as_ushort(ha);
}
DI uint32_t cvtf16x2(float f0, float f1) {             // {hi=f1, lo=f0}
    uint32_t r;
    asm("cvt.rn.f16x2.f32 %0, %1, %2;" : "=r"(r) : "f"(f1), "f"(f0));
    return r;
}

// ---------------------------------------------------------------------------
// Merged prep: fold BN, transpose to [n][k], split (fp16 for w1/w4/w5,
// bf16 for w2); biases.
// ---------------------------------------------------------------------------
__global__ void prep_all(const float* __restrict__ w_pw0, const float* __restrict__ w_pw1,
                         const float* __restrict__ w_vp,  const float* __restrict__ w_om,
                         const float* __restrict__ w_op,
                         const float* __restrict__ bn1_g, const float* __restrict__ bn1_b,
                         const float* __restrict__ bn1_m, const float* __restrict__ bn1_v,
                         const float* __restrict__ bn2_g, const float* __restrict__ bn2_b,
                         const float* __restrict__ bn2_m, const float* __restrict__ bn2_v,
                         const float* __restrict__ b_vp,  const float* __restrict__ b_om)
{
    int idx = blockIdx.x * blockDim.x + threadIdx.x;
    if (idx < 73728) {
        float w; u16 *H, *L; int off; bool f16;
        if (idx < 16384) {                       // pw0 * BN1 : fp16
            int k = idx & 127;
            w = w_pw0[idx] * bn1_g[k] * rsqrtf(bn1_v[k] + EPS);
            H = g_w1h; L = g_w1l; off = idx; f16 = true;
        } else if (idx < 32768) {                // pw1 * BN2 : fp16
            int j = idx - 16384; int k = j & 127;
            w = w_pw1[j] * bn2_g[k] * rsqrtf(bn2_v[k] + EPS);
            H = g_w5h; L = g_w5l; off = j; f16 = true;
        } else if (idx < 49152) {                // w_op^T : fp16
            int j = idx - 32768; int n = j >> 7, k = j & 127;
            w = w_op[k * 128 + n];
            H = g_w4h; L = g_w4l; off = j; f16 = true;
        } else {                                 // [w_vp|w_om]^T padded : bf16
            int j = idx - 49152; int n = j >> 7, k = j & 127;
            w = (n < 128) ? w_vp[k * 128 + n] : ((n < 155) ? w_om[k * 32 + (n - 128)] : 0.f);
            H = g_w2h; L = g_w2l; off = j; f16 = false;
        }
        if (f16) {
            __half h = __float2half_rn(w);
            H[off] = __half_as_ushort(h);
            L[off] = __half_as_ushort(__float2half_rn(w - __half2float(h)));
        } else {
            __nv_bfloat16 h = __float2bfloat16(w);
            H[off] = __bfloat16_as_ushort(h);
            L[off] = __bfloat16_as_ushort(__float2bfloat16(w - __bfloat162float(h)));
        }
    } else if (idx < 73856) {
        int o = idx - 73728;
        float s = 0.f;
        for (int c = 0; c < 128; ++c) {
            float sc = bn1_g[c] * rsqrtf(bn1_v[c] + EPS);
            s += w_pw0[o * 128 + c] * (bn1_b[c] - bn1_m[c] * sc);
        }
        g_bias0[o] = s;
    } else if (idx < 73984) {
        int o = idx - 73856;
        float s = 0.f;
        for (int c = 0; c < 128; ++c) {
            float sc = bn2_g[c] * rsqrtf(bn2_v[c] + EPS);
            s += w_pw1[o * 128 + c] * (bn2_b[c] - bn2_m[c] * sc);
        }
        g_bias1[o] = s;
    } else if (idx < 74176) {
        int j = idx - 73984;
        g_bcat[j] = (j < 128) ? b_vp[j] : ((j < 155) ? b_om[j - 128] : 0.f);
        g_zero[j] = 0.f;
    }
}

// ---------------------------------------------------------------------------
// Persistent chunk-loop HMMA GEMM.
//  FP16=true : A single fp16, B fp16 hi/lo (exact split), 2 passes
//  FP16=false: A bf16 hi/lo,  B bf16 hi/lo, 3 passes (AhBh + AhBl + AlBh)
//  AKM=true  : A read fp32 k-major (NCHW raw view), frags via LDS+cvt (FP16)
// MODE 0: fp32 row-major reg stores (token-major, ldo)
// MODE 1: raw-reshape scatter (B,C,HW)->(B,HW,C) direction ONLY (gemm1->gemm2);
//         OUTPAIR: bf16 hi/lo pair planes.
// MODE 2: fp32 NCHW final output
// 8 warps = 2m(32) x 4n(N/4); CH=64 chunks, cp.async double buffer.
// ---------------------------------------------------------------------------
template<int N, int MODE, bool AKM, bool FP16, bool OUTPAIR>
__global__ void __launch_bounds__(256, 1)
gemm_mma(const float* __restrict__ Af,
         const u16* __restrict__ A0, const u16* __restrict__ A1,
         const u16* __restrict__ B0, const u16* __restrict__ B1,
         const float* __restrict__ biasj,
         float* __restrict__ outF, int ldo,
         u16* __restrict__ outH, u16* __restrict__ outL)
{
    constexpr int NW = N / 4;
    constexpr int NT = NW / 8;
    constexpr int NP = NW / 16;
    constexpr int BOFF = 2 * N * 256;
    constexpr int APL = FP16 ? 1 : 2;                       // A planes (!AKM)
    constexpr int ABUF = AKM ? (128 * 272) : (CH * 256 * APL);
    constexpr int ldp = N + 1;

    extern __shared__ char sm[];
    const uint32_t uSM = smem_u32(sm);
    const uint32_t uBh = uSM, uBl = uSM + N * 256;
    float* stage = (float*)(sm + BOFF + 2 * ABUF);

    const int t = threadIdx.x, w = t >> 5, l = t & 31;
    const int wm = w & 1, wn = w >> 1;
    const int nb0 = wn * NW;

    const int cbase = (l & 3) * 2;
    float bj0[NT], bj1[NT];
#pragma unroll
    for (int nt = 0; nt < NT; nt++) {
        int col = nb0 + nt * 8 + cbase;
        bj0[nt] = biasj[col];
        bj1[nt] = biasj[col + 1];
    }

    // B load (once)
    {
        const uint4* sh_ = (const uint4*)B0;
        const uint4* sl_ = (const uint4*)B1;
        for (int i = t; i < N * 16; i += 256) {
            int r = i >> 4, c = i & 15;
            uint32_t o = tile_off(r, c);
            cpa16(uBh + o, sh_ + i);
            cpa16(uBl + o, sl_ + i);
        }
    }
    cpa_commit();

    auto loadA = [&](uint32_t dst, int cid_) {
        size_t m0 = (size_t)cid_ * CH;
        if constexpr (AKM) {
            const float* base = Af + (m0 >> 12) * 524288 + (m0 & 4095);
            for (int i = t; i < 2048; i += 256) {
                int k = i >> 4, u = i & 15;
                cpa16(dst + (uint32_t)(k * 272 + u * 16), base + (size_t)k * 4096 + u * 4);
            }
        } else {
            const uint4* s0 = (const uint4*)(A0 + m0 * 128);
            for (int i = t; i < 1024; i += 256) {
                int r = i >> 4, c = i & 15;
                cpa16(dst + tile_off(r, c), s0 + i);
            }
            if constexpr (!FP16) {
                const uint4* s1 = (const uint4*)(A1 + m0 * 128);
                for (int i = t; i < 1024; i += 256) {
                    int r = i >> 4, c = i & 15;
                    cpa16(dst + 16384 + tile_off(r, c), s1 + i);
                }
            }
        }
    };

    int cid = blockIdx.x;
    loadA(uSM + BOFF, cid);
    cpa_commit();

    const int arow_lo = wm * 32 + (l & 15);
    const int akhalf = l >> 4;
    const int brow_off = (l & 7) + ((l & 16) >> 1);
    const int bkhalf = (l >> 3) & 1;
    const int mfrag = wm * 32 + (l >> 2);
    const int kfrag = (l & 3) * 2;

    int p = 0;
    while (cid < CHUNKS) {
        const int nxt = cid + (int)gridDim.x;
        const bool hasnext = nxt < CHUNKS;
        if (hasnext) {
            loadA(uSM + BOFF + (p ^ 1) * ABUF, nxt);
            cpa_commit();
            cpa_wait1();
        } else {
            cpa_wait0();
        }
        __syncthreads();

        const uint32_t uA = uSM + BOFF + p * ABUF;
        const float* tileA = (const float*)(sm + BOFF + p * ABUF);

        float d[2][NT][4];
#pragma unroll
        for (int mt = 0; mt < 2; mt++)
#pragma unroll
            for (int nt = 0; nt < NT; nt++)
#pragma unroll
                for (int i = 0; i < 4; i++) d[mt][nt][i] = 0.f;

#pragma unroll
        for (int ks = 0; ks < 8; ks++) {
            uint32_t bh[NP][4], bl[NP][4];
#pragma unroll
            for (int np = 0; np < NP; np++) {
                uint32_t off = tile_off(nb0 + np * 16 + brow_off, 2 * ks + bkhalf);
                ldsm4(bh[np], uBh + off);
                ldsm4(bl[np], uBl + off);
            }
            if constexpr (FP16) {
                uint32_t a[2][4];
                if constexpr (AKM) {
#pragma unroll
                    for (int mt = 0; mt < 2; mt++) {
                        int mlo = mfrag + mt * 16;
                        int k0 = ks * 16 + kfrag;
                        a[mt][0] = cvtf16x2(tileA[(k0    ) * 68 + mlo],
                                            tileA[(k0 + 1) * 68 + mlo]);
                        a[mt][1] = cvtf16x2(tileA[(k0    ) * 68 + mlo + 8],
                                            tileA[(k0 + 1) * 68 + mlo + 8]);
                        a[mt][2] = cvtf16x2(tileA[(k0 + 8) * 68 + mlo],
                                            tileA[(k0 + 9) * 68 + mlo]);
                        a[mt][3] = cvtf16x2(tileA[(k0 + 8) * 68 + mlo + 8],
                                            tileA[(k0 + 9) * 68 + mlo + 8]);
                    }
                } else {
#pragma unroll
                    for (int mt = 0; mt < 2; mt++)
                        ldsm4(a[mt], uA + tile_off(arow_lo + mt * 16, 2 * ks + akhalf));
                }
                // pass 1: A*Bh
#pragma unroll
                for (int np = 0; np < NP; np++)
#pragma unroll
                    for (int mt = 0; mt < 2; mt++) {
                        mma_k16<true>(d[mt][2 * np],     a[mt], bh[np][0], bh[np][1]);
                        mma_k16<true>(d[mt][2 * np + 1], a[mt], bh[np][2], bh[np][3]);
                    }
                // pass 2: A*Bl
#pragma unroll
                for (int np = 0; np < NP; np++)
#pragma unroll
                    for (int mt = 0; mt < 2; mt++) {
                        mma_k16<true>(d[mt][2 * np],     a[mt], bl[np][0], bl[np][1]);
                        mma_k16<true>(d[mt][2 * np + 1], a[mt], bl[np][2], bl[np][3]);
                    }
            } else {
                uint32_t ah[2][4], al[2][4];
#pragma unroll
                for (int mt = 0; mt < 2; mt++) {
                    uint32_t off = tile_off(arow_lo + mt * 16, 2 * ks + akhalf);
                    ldsm4(ah[mt], uA + off);
                    ldsm4(al[mt], uA + 16384 + off);
                }
#pragma unroll
                for (int np = 0; np < NP; np++)
#pragma unroll
                    for (int mt = 0; mt < 2; mt++) {
                        mma_k16<false>(d[mt][2 * np],     ah[mt], bh[np][0], bh[np][1]);
                        mma_k16<false>(d[mt][2 * np + 1], ah[mt], bh[np][2], bh[np][3]);
                    }
#pragma unroll
                for (int np = 0; np < NP; np++)
#pragma unroll
                    for (int mt = 0; mt < 2; mt++) {
                        mma_k16<false>(d[mt][2 * np],     ah[mt], bl[np][0], bl[np][1]);
                        mma_k16<false>(d[mt][2 * np + 1], ah[mt], bl[np][2], bl[np][3]);
                    }
#pragma unroll
                for (int np = 0; np < NP; np++)
#pragma unroll
                    for (int mt = 0; mt < 2; mt++) {
                        mma_k16<false>(d[mt][2 * np],     al[mt], bh[np][0], bh[np][1]);
                        mma_k16<false>(d[mt][2 * np + 1], al[mt], bh[np][2], bh[np][3]);
                    }
            }
        }

        const size_t m0 = (size_t)cid * CH;
        const int rloc = wm * 32 + (l >> 2);

        if (MODE == 0) {
#pragma unroll
            for (int mt = 0; mt < 2; mt++)
#pragma unroll
                for (int nt = 0; nt < NT; nt++) {
                    int row = rloc + mt * 16;
                    int col = nb0 + nt * 8 + cbase;
                    float2 v0 = make_float2(d[mt][nt][0] + bj0[nt], d[mt][nt][1] + bj1[nt]);
                    float2 v1 = make_float2(d[mt][nt][2] + bj0[nt], d[mt][nt][3] + bj1[nt]);
                    *(float2*)(outF + (m0 + row) * (size_t)ldo + col) = v0;
                    *(float2*)(outF + (m0 + row + 8) * (size_t)ldo + col) = v1;
                }
        } else {
#pragma unroll
            for (int mt = 0; mt < 2; mt++)
#pragma unroll
                for (int nt = 0; nt < NT; nt++) {
                    int row = rloc + mt * 16;
                    int col = nb0 + nt * 8 + cbase;
                    stage[row * ldp + col]           = d[mt][nt][0] + bj0[nt];
                    stage[row * ldp + col + 1]       = d[mt][nt][1] + bj1[nt];
                    stage[(row + 8) * ldp + col]     = d[mt][nt][2] + bj0[nt];
                    stage[(row + 8) * ldp + col + 1] = d[mt][nt][3] + bj1[nt];
                }
            __syncthreads();
            if (MODE == 1) {
                // (B,C,HW)->(B,HW,C) scatter: D[(b,s)][n] -> A'[b*4096+n*32+(s>>7)][s&127]
                const int b  = (int)(m0 >> 12);
                const int sh = (int)((m0 & 4095) >> 7);
                const int cb = (int)(m0 & 64);
                for (int i = t; i < N * 16; i += 256) {
                    int n = i >> 4, q = i & 15, j0 = q * 4;
                    float v0 = stage[(j0 + 0) * ldp + n], v1 = stage[(j0 + 1) * ldp + n];
                    float v2 = stage[(j0 + 2) * ldp + n], v3 = stage[(j0 + 3) * ldp + n];
                    size_t row = (size_t)b * 4096 + (size_t)n * 32 + sh;
                    if constexpr (OUTPAIR) {
                        uint2 hq, lq; float r0, r1, r2, r3;
                        hq.x = pksplit(v0, v1, r0, r1); hq.y = pksplit(v2, v3, r2, r3);
                        lq.x = pk(r0, r1);              lq.y = pk(r2, r3);
                        ((uint2*)(outH + row * 128 + cb))[q] = hq;
                        ((uint2*)(outL + row * 128 + cb))[q] = lq;
                    } else {
                        uint2 o;
                        o.x = cvtf16x2(v0, v1);
                        o.y = cvtf16x2(v2, v3);
                        ((uint2*)(outH + row * 128 + cb))[q] = o;
                    }
                }
            } else {
                // NCHW: D[(b, s0+j)][n] -> out[b][n][s0+j]
                const int b  = (int)(m0 >> 12);
                const int s0 = (int)(m0 & 4095);
                for (int i = t; i < N * 16; i += 256) {
                    int n = i >> 4, q = i & 15, j0 = q * 4;
                    float4 v = make_float4(stage[(j0 + 0) * ldp + n], stage[(j0 + 1) * ldp + n],
                                           stage[(j0 + 2) * ldp + n], stage[(j0 + 3) * ldp + n]);
                    *(float4*)(outF + (size_t)b * 524288 + (size_t)n * 4096 + s0 + j0) = v;
                }
            }
        }
        __syncthreads();
        p ^= 1;
        cid = nxt;
    }
}

// ---------------------------------------------------------------------------
// DCNv4 core (fp32) -> fp16 single-plane output
// ---------------------------------------------------------------------------
__global__ void dcn_kernel(const float* __restrict__ vpom, u16* __restrict__ oh)
{
    const int warp = threadIdx.x >> 5;
    const int lane = threadIdx.x & 31;
    const int pos  = blockIdx.x * 8 + warp;
    const int b = pos >> 12;
    const int s = pos & 4095;
    const int h = s >> 6;
    const int w = s & 63;

    const float* omp = vpom + (size_t)pos * 192 + 128;
    float omv = (lane < 27) ? omp[lane] : 0.f;

    const float* vb = vpom + ((size_t)b << 12) * 192;
    const int coff = lane << 2;

    float4 acc = make_float4(0.f, 0.f, 0.f, 0.f);

#pragma unroll
    for (int k = 0; k < 9; ++k) {
        float dx = __shfl_sync(0xffffffffu, omv, 3 * k);
        float dy = __shfl_sync(0xffffffffu, omv, 3 * k + 1);
        float m  = __shfl_sync(0xffffffffu, omv, 3 * k + 2);
        float px = (float)(w + (k % 3) - 1) + dx;
        float py = (float)(h + (k / 3) - 1) + dy;
        float xf = floorf(px), yf = floorf(py);
        float fx = px - xf,    fy = py - yf;
        int x0 = (int)xf, y0 = (int)yf;
#pragma unroll
        for (int cy = 0; cy < 2; ++cy) {
#pragma unroll
            for (int cx = 0; cx < 2; ++cx) {
                int xi = x0 + cx, yi = y0 + cy;
                float wt = (cx ? fx : 1.f - fx) * (cy ? fy : 1.f - fy) * m;
                if (xi < 0 || xi > 63 || yi < 0 || yi > 63) wt = 0.f;
                int xc = min(max(xi, 0), 63);
                int yc = min(max(yi, 0), 63);
                const float4 v = *(const float4*)(vb + (size_t)(yc * 64 + xc) * 192 + coff);
                acc.x += wt * v.x; acc.y += wt * v.y;
                acc.z += wt * v.z; acc.w += wt * v.w;
            }
        }
    }
    uint2 o;
    o.x = cvtf16x2(acc.x, acc.y);
    o.y = cvtf16x2(acc.z, acc.w);
    *(uint2*)(oh + (size_t)pos * 128 + coff) = o;
}

// ---------------------------------------------------------------------------
// Launcher
// ---------------------------------------------------------------------------
extern "C" void kernel_launch(void* const* d_in, const int* in_sizes, int n_in,
                              void* d_out, int out_size)
{
    (void)in_sizes; (void)n_in; (void)out_size;
    const float* x     = (const float*)d_in[0];
    const float* bn1_g = (const float*)d_in[1];
    const float* bn1_b = (const float*)d_in[2];
    const float* bn1_m = (const float*)d_in[3];
    const float* bn1_v = (const float*)d_in[4];
    const float* w_pw0 = (const float*)d_in[5];
    const float* w_vp  = (const float*)d_in[6];
    const float* b_vp  = (const float*)d_in[7];
    const float* w_om  = (const float*)d_in[8];
    const float* b_om  = (const float*)d_in[9];
    const float* w_op  = (const float*)d_in[10];
    const float* bn2_g = (const float*)d_in[11];
    const float* bn2_b = (const float*)d_in[12];
    const float* bn2_m = (const float*)d_in[13];
    const float* bn2_v = (const float*)d_in[14];
    const float* w_pw1 = (const float*)d_in[15];
    float* out = (float*)d_out;

    u16 *a2h, *a2l, *dcn;
    u16 *w1h, *w1l, *w2h, *w2l, *w4h, *w4l, *w5h, *w5l;
    float *vpom, *op, *bias0, *bias1, *bcat, *zero;
    cudaGetSymbolAddress((void**)&a2h, g_a2_hi);  cudaGetSymbolAddress((void**)&a2l, g_a2_lo);
    cudaGetSymbolAddress((void**)&dcn, g_dcn);    cudaGetSymbolAddress((void**)&op, g_op);
    cudaGetSymbolAddress((void**)&w1h, g_w1h);    cudaGetSymbolAddress((void**)&w1l, g_w1l);
    cudaGetSymbolAddress((void**)&w2h, g_w2h);    cudaGetSymbolAddress((void**)&w2l, g_w2l);
    cudaGetSymbolAddress((void**)&w4h, g_w4h);    cudaGetSymbolAddress((void**)&w4l, g_w4l);
    cudaGetSymbolAddress((void**)&w5h, g_w5h);    cudaGetSymbolAddress((void**)&w5l, g_w5l);
    cudaGetSymbolAddress((void**)&vpom, g_vpom);
    cudaGetSymbolAddress((void**)&bias0, g_bias0); cudaGetSymbolAddress((void**)&bias1, g_bias1);
    cudaGetSymbolAddress((void**)&bcat, g_bcat);  cudaGetSymbolAddress((void**)&zero, g_zero);

    // smem: B(2*N*256) + A dbuf + stage (MODE1/2 only)
    const int SM_G1 = 65536 + 2 * 128 * 272 + 64 * 129 * 4;     // gemm1 (AKM,fp16,MODE1)
    const int SM_G2 = 98304 + 2 * 2 * 64 * 256;                 // gemm2 (bf16x3,MODE0)
    const int SM_G4 = 65536 + 2 * 1 * 64 * 256;                 // gemm4 (fp16,MODE0)
    const int SM_G5 = 65536 + 2 * 128 * 272 + 64 * 129 * 4;     // gemm5 (AKM,fp16,MODE2)
    cudaFuncSetAttribute((const void*)gemm_mma<128, 1, true,  true,  true>,
                         cudaFuncAttributeMaxDynamicSharedMemorySize, SM_G1);
    cudaFuncSetAttribute((const void*)gemm_mma<192, 0, false, false, false>,
                         cudaFuncAttributeMaxDynamicSharedMemorySize, SM_G2);
    cudaFuncSetAttribute((const void*)gemm_mma<128, 0, false, true,  false>,
                         cudaFuncAttributeMaxDynamicSharedMemorySize, SM_G4);
    cudaFuncSetAttribute((const void*)gemm_mma<128, 2, true,  true,  false>,
                         cudaFuncAttributeMaxDynamicSharedMemorySize, SM_G5);

    const int GRID = 148;

    prep_all<<<290, 256>>>(w_pw0, w_pw1, w_vp, w_om, w_op,
                           bn1_g, bn1_b, bn1_m, bn1_v,
                           bn2_g, bn2_b, bn2_m, bn2_v, b_vp, b_om);

    // 1) x1 = x(NCHW fp32 k-major) @ w1^T + bias0 -> bf16 pair scatter
    //    ((B,C,HW)->(B,HW,C) raw-reshape direction; gemm2's A layout)
    gemm_mma<128, 1, true, true, true><<<GRID, 256, SM_G1>>>(
        x, nullptr, nullptr, w1h, w1l, bias0, nullptr, 0, a2h, a2l);

    // 2) vpom = x1_view @ [w_vp|w_om]^T + bcat  (bf16x3 exact-ish, fp32 out)
    gemm_mma<192, 0, false, false, false><<<GRID, 256, SM_G2>>>(
        nullptr, a2h, a2l, w2h, w2l, bcat, vpom, 192, nullptr, nullptr);

    // 3) DCNv4 core -> fp16 single plane
    dcn_kernel<<<4096, 256>>>(vpom, dcn);

    // 4) op = dcn @ w_op -> fp32 token-major (which IS the NCHW raw view for 5)
    gemm_mma<128, 0, false, true, false><<<GRID, 256, SM_G4>>>(
        nullptr, dcn, nullptr, w4h, w4l, zero, op, 128, nullptr, nullptr);

    // 5) out = (BN2-folded pw1) @ op(NCHW view, fp32 k-major read) -> fp32 NCHW
    gemm_mma<128, 2, true, true, false><<<GRID, 256, SM_G5>>>(
        op, nullptr, nullptr, w5h, w5l, bias1, out, 0, nullptr, nullptr);
}

// round 11
// speedup vs baseline: 1.2799x; 1.0837x over previous
#include <cuda_runtime.h>
#include <cuda_bf16.h>
#include <cuda_fp16.h>
#include <cstdint>
#include <math.h>

#define DI __device__ __forceinline__
typedef unsigned short u16;

constexpr int TOK = 32768;           // 8 * 64 * 64
constexpr float EPS = 1e-5f;
constexpr int CH = 64;               // tokens per chunk
constexpr int CHUNKS = TOK / CH;     // 512

// ---------------------------------------------------------------------------
// Device scratch
// ---------------------------------------------------------------------------
__device__ __align__(16) u16   g_a2[TOK * 128];        // x1, fp16 single plane
__device__ __align__(16) float g_vpom[TOK * 192];
__device__ __align__(16) u16   g_dcn[TOK * 128];       // fp16 single
__device__ __align__(16) float g_op[TOK * 128];        // fp32 token-major

__device__ __align__(16) u16 g_w1h[128 * 128], g_w1l[128 * 128];   // fp16
__device__ __align__(16) u16 g_w2h[192 * 128], g_w2l[192 * 128];   // fp16
__device__ __align__(16) u16 g_w4h[128 * 128], g_w4l[128 * 128];   // fp16
__device__ __align__(16) u16 g_w5h[128 * 128], g_w5l[128 * 128];   // fp16
__device__ float g_bias0[128], g_bias1[128], g_bcat[192], g_zero[192];

// ---------------------------------------------------------------------------
// Helpers
// ---------------------------------------------------------------------------
DI uint32_t smem_u32(const void* p) {
    uint32_t a;
    asm("{ .reg .u64 t; cvta.to.shared.u64 t, %1; cvt.u32.u64 %0, t; }" : "=r"(a) : "l"(p));
    return a;
}

DI void cpa16(uint32_t dst, const void* src) {
    asm volatile("{ .reg .u64 g; cvta.to.global.u64 g, %1; "
                 "cp.async.cg.shared.global [%0], [g], 16; }"
                 :: "r"(dst), "l"(src));
}
DI void cpa_commit() { asm volatile("cp.async.commit_group;" ::: "memory"); }
DI void cpa_wait0() { asm volatile("cp.async.wait_group 0;" ::: "memory"); }
DI void cpa_wait1() { asm volatile("cp.async.wait_group 1;" ::: "memory"); }

DI void ldsm4(uint32_t (&r)[4], uint32_t addr) {
    asm volatile("ldmatrix.sync.aligned.m8n8.x4.shared.b16 {%0,%1,%2,%3}, [%4];"
                 : "=r"(r[0]), "=r"(r[1]), "=r"(r[2]), "=r"(r[3]) : "r"(addr));
}

DI void mma_f16(float (&d)[4], const uint32_t (&a)[4], uint32_t b0, uint32_t b1) {
    asm volatile("mma.sync.aligned.m16n8k16.row.col.f32.f16.f16.f32 "
                 "{%0,%1,%2,%3}, {%4,%5,%6,%7}, {%8,%9}, {%0,%1,%2,%3};"
                 : "+f"(d[0]), "+f"(d[1]), "+f"(d[2]), "+f"(d[3])
                 : "r"(a[0]), "r"(a[1]), "r"(a[2]), "r"(a[3]), "r"(b0), "r"(b1));
}

// XOR-swizzled 16-bit tile: row stride 256 B (128 elems), 16B chunk c -> c ^ (row&7)
DI uint32_t tile_off(int r, int chunk) { return (uint32_t)(r * 256 + ((chunk ^ (r & 7)) << 4)); }

DI uint32_t cvtf16x2(float f0, float f1) {             // {hi=f1, lo=f0}
    uint32_t r;
    asm("cvt.rn.f16x2.f32 %0, %1, %2;" : "=r"(r) : "f"(f1), "f"(f0));
    return r;
}

// ---------------------------------------------------------------------------
// Merged prep: fold BN, transpose to [n][k], split all weights to fp16 hi/lo
// (exact two-term split), plus biases.
// ---------------------------------------------------------------------------
__global__ void prep_all(const float* __restrict__ w_pw0, const float* __restrict__ w_pw1,
                         const float* __restrict__ w_vp,  const float* __restrict__ w_om,
                         const float* __restrict__ w_op,
                         const float* __restrict__ bn1_g, const float* __restrict__ bn1_b,
                         const float* __restrict__ bn1_m, const float* __restrict__ bn1_v,
                         const float* __restrict__ bn2_g, const float* __restrict__ bn2_b,
                         const float* __restrict__ bn2_m, const float* __restrict__ bn2_v,
                         const float* __restrict__ b_vp,  const float* __restrict__ b_om)
{
    int idx = blockIdx.x * blockDim.x + threadIdx.x;
    if (idx < 73728) {
        float w; u16 *H, *L; int off;
        if (idx < 16384) {                       // pw0 * BN1
            int k = idx & 127;
            w = w_pw0[idx] * bn1_g[k] * rsqrtf(bn1_v[k] + EPS);
            H = g_w1h; L = g_w1l; off = idx;
        } else if (idx < 32768) {                // pw1 * BN2
            int j = idx - 16384; int k = j & 127;
            w = w_pw1[j] * bn2_g[k] * rsqrtf(bn2_v[k] + EPS);
            H = g_w5h; L = g_w5l; off = j;
        } else if (idx < 49152) {                // w_op^T
            int j = idx - 32768; int n = j >> 7, k = j & 127;
            w = w_op[k * 128 + n];
            H = g_w4h; L = g_w4l; off = j;
        } else {                                 // [w_vp|w_om]^T padded to 192
            int j = idx - 49152; int n = j >> 7, k = j & 127;
            w = (n < 128) ? w_vp[k * 128 + n] : ((n < 155) ? w_om[k * 32 + (n - 128)] : 0.f);
            H = g_w2h; L = g_w2l; off = j;
        }
        __half h = __float2half_rn(w);
        H[off] = __half_as_ushort(h);
        L[off] = __half_as_ushort(__float2half_rn(w - __half2float(h)));
    } else if (idx < 73856) {
        int o = idx - 73728;
        float s = 0.f;
        for (int c = 0; c < 128; ++c) {
            float sc = bn1_g[c] * rsqrtf(bn1_v[c] + EPS);
            s += w_pw0[o * 128 + c] * (bn1_b[c] - bn1_m[c] * sc);
        }
        g_bias0[o] = s;
    } else if (idx < 73984) {
        int o = idx - 73856;
        float s = 0.f;
        for (int c = 0; c < 128; ++c) {
            float sc = bn2_g[c] * rsqrtf(bn2_v[c] + EPS);
            s += w_pw1[o * 128 + c] * (bn2_b[c] - bn2_m[c] * sc);
        }
        g_bias1[o] = s;
    } else if (idx < 74176) {
        int j = idx - 73984;
        g_bcat[j] = (j < 128) ? b_vp[j] : ((j < 155) ? b_om[j - 128] : 0.f);
        g_zero[j] = 0.f;
    }
}

// ---------------------------------------------------------------------------
// Persistent chunk-loop HMMA GEMM (fp16 2-pass: A single fp16, B exact
// fp16 hi/lo split; fp32 accum).
//  AKM=true : A read fp32 k-major (NCHW raw view); frags via LDS + cvt.
// MODE 0: fp32 row-major reg stores (token-major, ldo)
// MODE 1: raw-reshape scatter (B,C,HW)->(B,HW,C), fp16 single plane out
// MODE 2: fp32 NCHW final output
// 8 warps = 2m(32) x 4n(N/4); CH=64 chunks, cp.async double buffer.
// ---------------------------------------------------------------------------
template<int N, int MODE, bool AKM>
__global__ void __launch_bounds__(256, 1)
gemm_mma(const float* __restrict__ Af, const u16* __restrict__ A0,
         const u16* __restrict__ B0, const u16* __restrict__ B1,
         const float* __restrict__ biasj,
         float* __restrict__ outF, int ldo, u16* __restrict__ outH)
{
    constexpr int NW = N / 4;
    constexpr int NT = NW / 8;
    constexpr int NP = NW / 16;
    constexpr int BOFF = 2 * N * 256;
    constexpr int ABUF = AKM ? (128 * 272) : (CH * 256);
    constexpr int ldp = N + 1;

    extern __shared__ char sm[];
    const uint32_t uSM = smem_u32(sm);
    const uint32_t uBh = uSM, uBl = uSM + N * 256;
    float* stage = (float*)(sm + BOFF + 2 * ABUF);

    const int t = threadIdx.x, w = t >> 5, l = t & 31;
    const int wm = w & 1, wn = w >> 1;
    const int nb0 = wn * NW;

    const int cbase = (l & 3) * 2;
    float bj0[NT], bj1[NT];
#pragma unroll
    for (int nt = 0; nt < NT; nt++) {
        int col = nb0 + nt * 8 + cbase;
        bj0[nt] = biasj[col];
        bj1[nt] = biasj[col + 1];
    }

    // B load (once)
    {
        const uint4* sh_ = (const uint4*)B0;
        const uint4* sl_ = (const uint4*)B1;
        for (int i = t; i < N * 16; i += 256) {
            int r = i >> 4, c = i & 15;
            uint32_t o = tile_off(r, c);
            cpa16(uBh + o, sh_ + i);
            cpa16(uBl + o, sl_ + i);
        }
    }
    cpa_commit();

    auto loadA = [&](uint32_t dst, int cid_) {
        size_t m0 = (size_t)cid_ * CH;
        if constexpr (AKM) {
            const float* base = Af + (m0 >> 12) * 524288 + (m0 & 4095);
            for (int i = t; i < 2048; i += 256) {
                int k = i >> 4, u = i & 15;
                cpa16(dst + (uint32_t)(k * 272 + u * 16), base + (size_t)k * 4096 + u * 4);
            }
        } else {
            const uint4* s0 = (const uint4*)(A0 + m0 * 128);
            for (int i = t; i < 1024; i += 256) {
                int r = i >> 4, c = i & 15;
                cpa16(dst + tile_off(r, c), s0 + i);
            }
        }
    };

    int cid = blockIdx.x;
    loadA(uSM + BOFF, cid);
    cpa_commit();

    const int arow_lo = wm * 32 + (l & 15);
    const int akhalf = l >> 4;
    const int brow_off = (l & 7) + ((l & 16) >> 1);
    const int bkhalf = (l >> 3) & 1;
    const int mfrag = wm * 32 + (l >> 2);
    const int kfrag = (l & 3) * 2;

    int p = 0;
    while (cid < CHUNKS) {
        const int nxt = cid + (int)gridDim.x;
        const bool hasnext = nxt < CHUNKS;
        if (hasnext) {
            loadA(uSM + BOFF + (p ^ 1) * ABUF, nxt);
            cpa_commit();
            cpa_wait1();
        } else {
            cpa_wait0();
        }
        __syncthreads();

        const uint32_t uA = uSM + BOFF + p * ABUF;
        const float* tileA = (const float*)(sm + BOFF + p * ABUF);

        float d[2][NT][4];
#pragma unroll
        for (int mt = 0; mt < 2; mt++)
#pragma unroll
            for (int nt = 0; nt < NT; nt++)
#pragma unroll
                for (int i = 0; i < 4; i++) d[mt][nt][i] = 0.f;

#pragma unroll
        for (int ks = 0; ks < 8; ks++) {
            uint32_t bh[NP][4], bl[NP][4];
#pragma unroll
            for (int np = 0; np < NP; np++) {
                uint32_t off = tile_off(nb0 + np * 16 + brow_off, 2 * ks + bkhalf);
                ldsm4(bh[np], uBh + off);
                ldsm4(bl[np], uBl + off);
            }
            uint32_t a[2][4];
            if constexpr (AKM) {
#pragma unroll
                for (int mt = 0; mt < 2; mt++) {
                    int mlo = mfrag + mt * 16;
                    int k0 = ks * 16 + kfrag;
                    a[mt][0] = cvtf16x2(tileA[(k0    ) * 68 + mlo],
                                        tileA[(k0 + 1) * 68 + mlo]);
                    a[mt][1] = cvtf16x2(tileA[(k0    ) * 68 + mlo + 8],
                                        tileA[(k0 + 1) * 68 + mlo + 8]);
                    a[mt][2] = cvtf16x2(tileA[(k0 + 8) * 68 + mlo],
                                        tileA[(k0 + 9) * 68 + mlo]);
                    a[mt][3] = cvtf16x2(tileA[(k0 + 8) * 68 + mlo + 8],
                                        tileA[(k0 + 9) * 68 + mlo + 8]);
                }
            } else {
#pragma unroll
                for (int mt = 0; mt < 2; mt++)
                    ldsm4(a[mt], uA + tile_off(arow_lo + mt * 16, 2 * ks + akhalf));
            }
            // pass 1: A*Bh
#pragma unroll
            for (int np = 0; np < NP; np++)
#pragma unroll
                for (int mt = 0; mt < 2; mt++) {
                    mma_f16(d[mt][2 * np],     a[mt], bh[np][0], bh[np][1]);
                    mma_f16(d[mt][2 * np + 1], a[mt], bh[np][2], bh[np][3]);
                }
            // pass 2: A*Bl
#pragma unroll
            for (int np = 0; np < NP; np++)
#pragma unroll
                for (int mt = 0; mt < 2; mt++) {
                    mma_f16(d[mt][2 * np],     a[mt], bl[np][0], bl[np][1]);
                    mma_f16(d[mt][2 * np + 1], a[mt], bl[np][2], bl[np][3]);
                }
        }

        const size_t m0 = (size_t)cid * CH;
        const int rloc = wm * 32 + (l >> 2);

        if (MODE == 0) {
#pragma unroll
            for (int mt = 0; mt < 2; mt++)
#pragma unroll
                for (int nt = 0; nt < NT; nt++) {
                    int row = rloc + mt * 16;
                    int col = nb0 + nt * 8 + cbase;
                    float2 v0 = make_float2(d[mt][nt][0] + bj0[nt], d[mt][nt][1] + bj1[nt]);
                    float2 v1 = make_float2(d[mt][nt][2] + bj0[nt], d[mt][nt][3] + bj1[nt]);
                    *(float2*)(outF + (m0 + row) * (size_t)ldo + col) = v0;
                    *(float2*)(outF + (m0 + row + 8) * (size_t)ldo + col) = v1;
                }
        } else {
#pragma unroll
            for (int mt = 0; mt < 2; mt++)
#pragma unroll
                for (int nt = 0; nt < NT; nt++) {
                    int row = rloc + mt * 16;
                    int col = nb0 + nt * 8 + cbase;
                    stage[row * ldp + col]           = d[mt][nt][0] + bj0[nt];
                    stage[row * ldp + col + 1]       = d[mt][nt][1] + bj1[nt];
                    stage[(row + 8) * ldp + col]     = d[mt][nt][2] + bj0[nt];
                    stage[(row + 8) * ldp + col + 1] = d[mt][nt][3] + bj1[nt];
                }
            __syncthreads();
            if (MODE == 1) {
                // (B,C,HW)->(B,HW,C) scatter: D[(b,s)][n] -> A'[b*4096+n*32+(s>>7)][s&127]
                const int b  = (int)(m0 >> 12);
                const int sh = (int)((m0 & 4095) >> 7);
                const int cb = (int)(m0 & 64);
                for (int i = t; i < N * 16; i += 256) {
                    int n = i >> 4, q = i & 15, j0 = q * 4;
                    float v0 = stage[(j0 + 0) * ldp + n], v1 = stage[(j0 + 1) * ldp + n];
                    float v2 = stage[(j0 + 2) * ldp + n], v3 = stage[(j0 + 3) * ldp + n];
                    size_t row = (size_t)b * 4096 + (size_t)n * 32 + sh;
                    uint2 o;
                    o.x = cvtf16x2(v0, v1);
                    o.y = cvtf16x2(v2, v3);
                    ((uint2*)(outH + row * 128 + cb))[q] = o;
                }
            } else {
                // NCHW: D[(b, s0+j)][n] -> out[b][n][s0+j]
                const int b  = (int)(m0 >> 12);
                const int s0 = (int)(m0 & 4095);
                for (int i = t; i < N * 16; i += 256) {
                    int n = i >> 4, q = i & 15, j0 = q * 4;
                    float4 v = make_float4(stage[(j0 + 0) * ldp + n], stage[(j0 + 1) * ldp + n],
                                           stage[(j0 + 2) * ldp + n], stage[(j0 + 3) * ldp + n]);
                    *(float4*)(outF + (size_t)b * 524288 + (size_t)n * 4096 + s0 + j0) = v;
                }
            }
        }
        __syncthreads();
        p ^= 1;
        cid = nxt;
    }
}

// ---------------------------------------------------------------------------
// DCNv4 core v2 — setup-broadcast form.
// Lanes 0..8 compute the bilinear setup (4 weights + 4 clamped float-offsets)
// for kernel point k=lane; main loop shuffles them to all lanes; lanes then
// only do gather-load + FMA on their 4 channels. fp16 single-plane output.
// ---------------------------------------------------------------------------
__global__ void dcn_kernel(const float* __restrict__ vpom, u16* __restrict__ oh)
{
    const int warp = threadIdx.x >> 5;
    const int lane = threadIdx.x & 31;
    const int pos  = blockIdx.x * 8 + warp;
    const int b = pos >> 12;
    const int s = pos & 4095;
    const int h = s >> 6;
    const int w = s & 63;

    const float* omp = vpom + (size_t)pos * 192 + 128;
    float omv = (lane < 27) ? omp[lane] : 0.f;

    // --- setup (meaningful in lanes 0..8 only) ---
    float w00, w10, w01, w11;
    int   o00, o10, o01, o11;
    {
        const int k  = lane;                      // garbage for lane>=9, unused
        const unsigned FULL = 0xffffffffu;
        float dx = __shfl_sync(FULL, omv, (3 * k)     & 31);
        float dy = __shfl_sync(FULL, omv, (3 * k + 1) & 31);
        float m  = __shfl_sync(FULL, omv, (3 * k + 2) & 31);
        int ky = k / 3, kx = k - ky * 3;
        float px = (float)(w + kx - 1) + dx;
        float py = (float)(h + ky - 1) + dy;
        float xf = floorf(px), yf = floorf(py);
        float fx = px - xf, fy = py - yf;
        int x0 = (int)xf, y0 = (int)yf;
        int x1 = x0 + 1,  y1 = y0 + 1;
        float vx0 = (x0 >= 0 && x0 < 64) ? m : 0.f;
        float vx1 = (x1 >= 0 && x1 < 64) ? m : 0.f;
        float gy0 = (y0 >= 0 && y0 < 64) ? 1.f : 0.f;
        float gy1 = (y1 >= 0 && y1 < 64) ? 1.f : 0.f;
        float gx0 = 1.f - fx, gy0f = 1.f - fy;
        w00 = gx0 * gy0f * vx0 * gy0;
        w10 = fx  * gy0f * vx1 * gy0;
        w01 = gx0 * fy   * vx0 * gy1;
        w11 = fx  * fy   * vx1 * gy1;
        int xc0 = min(max(x0, 0), 63), xc1 = min(max(x1, 0), 63);
        int yc0 = min(max(y0, 0), 63), yc1 = min(max(y1, 0), 63);
        o00 = (yc0 * 64 + xc0) * 192;
        o10 = (yc0 * 64 + xc1) * 192;
        o01 = (yc1 * 64 + xc0) * 192;
        o11 = (yc1 * 64 + xc1) * 192;
    }

    const float* vbc = vpom + (((size_t)b << 12) * 192) + (lane << 2);
    float4 acc = make_float4(0.f, 0.f, 0.f, 0.f);
    const unsigned FULL = 0xffffffffu;

#pragma unroll
    for (int k = 0; k < 9; ++k) {
        int   a0 = __shfl_sync(FULL, o00, k);
        int   a1 = __shfl_sync(FULL, o10, k);
        int   a2 = __shfl_sync(FULL, o01, k);
        int   a3 = __shfl_sync(FULL, o11, k);
        float t0 = __shfl_sync(FULL, w00, k);
        float t1 = __shfl_sync(FULL, w10, k);
        float t2 = __shfl_sync(FULL, w01, k);
        float t3 = __shfl_sync(FULL, w11, k);
        float4 v0 = *(const float4*)(vbc + a0);
        float4 v1 = *(const float4*)(vbc + a1);
        float4 v2 = *(const float4*)(vbc + a2);
        float4 v3 = *(const float4*)(vbc + a3);
        acc.x += t0 * v0.x; acc.y += t0 * v0.y; acc.z += t0 * v0.z; acc.w += t0 * v0.w;
        acc.x += t1 * v1.x; acc.y += t1 * v1.y; acc.z += t1 * v1.z; acc.w += t1 * v1.w;
        acc.x += t2 * v2.x; acc.y += t2 * v2.y; acc.z += t2 * v2.z; acc.w += t2 * v2.w;
        acc.x += t3 * v3.x; acc.y += t3 * v3.y; acc.z += t3 * v3.z; acc.w += t3 * v3.w;
    }
    uint2 o;
    o.x = cvtf16x2(acc.x, acc.y);
    o.y = cvtf16x2(acc.z, acc.w);
    *(uint2*)(oh + (size_t)pos * 128 + (lane << 2)) = o;
}

// ---------------------------------------------------------------------------
// Launcher
// ---------------------------------------------------------------------------
extern "C" void kernel_launch(void* const* d_in, const int* in_sizes, int n_in,
                              void* d_out, int out_size)
{
    (void)in_sizes; (void)n_in; (void)out_size;
    const float* x     = (const float*)d_in[0];
    const float* bn1_g = (const float*)d_in[1];
    const float* bn1_b = (const float*)d_in[2];
    const float* bn1_m = (const float*)d_in[3];
    const float* bn1_v = (const float*)d_in[4];
    const float* w_pw0 = (const float*)d_in[5];
    const float* w_vp  = (const float*)d_in[6];
    const float* b_vp  = (const float*)d_in[7];
    const float* w_om  = (const float*)d_in[8];
    const float* b_om  = (const float*)d_in[9];
    const float* w_op  = (const float*)d_in[10];
    const float* bn2_g = (const float*)d_in[11];
    const float* bn2_b = (const float*)d_in[12];
    const float* bn2_m = (const float*)d_in[13];
    const float* bn2_v = (const float*)d_in[14];
    const float* w_pw1 = (const float*)d_in[15];
    float* out = (float*)d_out;

    u16 *a2, *dcn;
    u16 *w1h, *w1l, *w2h, *w2l, *w4h, *w4l, *w5h, *w5l;
    float *vpom, *op, *bias0, *bias1, *bcat, *zero;
    cudaGetSymbolAddress((void**)&a2, g_a2);
    cudaGetSymbolAddress((void**)&dcn, g_dcn);    cudaGetSymbolAddress((void**)&op, g_op);
    cudaGetSymbolAddress((void**)&w1h, g_w1h);    cudaGetSymbolAddress((void**)&w1l, g_w1l);
    cudaGetSymbolAddress((void**)&w2h, g_w2h);    cudaGetSymbolAddress((void**)&w2l, g_w2l);
    cudaGetSymbolAddress((void**)&w4h, g_w4h);    cudaGetSymbolAddress((void**)&w4l, g_w4l);
    cudaGetSymbolAddress((void**)&w5h, g_w5h);    cudaGetSymbolAddress((void**)&w5l, g_w5l);
    cudaGetSymbolAddress((void**)&vpom, g_vpom);
    cudaGetSymbolAddress((void**)&bias0, g_bias0); cudaGetSymbolAddress((void**)&bias1, g_bias1);
    cudaGetSymbolAddress((void**)&bcat, g_bcat);  cudaGetSymbolAddress((void**)&zero, g_zero);

    // smem: B(2*N*256) + A dbuf + stage (MODE1/2 only)
    const int SM_G1 = 65536 + 2 * 128 * 272 + 64 * 129 * 4;     // gemm1 (AKM, MODE1)
    const int SM_G2 = 98304 + 2 * 64 * 256;                     // gemm2 (MODE0)
    const int SM_G4 = 65536 + 2 * 64 * 256;                     // gemm4 (MODE0)
    const int SM_G5 = 65536 + 2 * 128 * 272 + 64 * 129 * 4;     // gemm5 (AKM, MODE2)
    cudaFuncSetAttribute((const void*)gemm_mma<128, 1, true>,
                         cudaFuncAttributeMaxDynamicSharedMemorySize, SM_G1);
    cudaFuncSetAttribute((const void*)gemm_mma<192, 0, false>,
                         cudaFuncAttributeMaxDynamicSharedMemorySize, SM_G2);
    cudaFuncSetAttribute((const void*)gemm_mma<128, 0, false>,
                         cudaFuncAttributeMaxDynamicSharedMemorySize, SM_G4);
    cudaFuncSetAttribute((const void*)gemm_mma<128, 2, true>,
                         cudaFuncAttributeMaxDynamicSharedMemorySize, SM_G5);

    const int GRID = 148;

    prep_all<<<290, 256>>>(w_pw0, w_pw1, w_vp, w_om, w_op,
                           bn1_g, bn1_b, bn1_m, bn1_v,
                           bn2_g, bn2_b, bn2_m, bn2_v, b_vp, b_om);

    // 1) x1 = x(NCHW fp32 k-major) @ w1^T + bias0 -> fp16 single scatter
    //    ((B,C,HW)->(B,HW,C) raw-reshape direction; gemm2's A layout)
    gemm_mma<128, 1, true><<<GRID, 256, SM_G1>>>(
        x, nullptr, w1h, w1l, bias0, nullptr, 0, a2);

    // 2) vpom = x1_view @ [w_vp|w_om]^T + bcat  (fp16 2-pass, fp32 out)
    gemm_mma<192, 0, false><<<GRID, 256, SM_G2>>>(
        nullptr, a2, w2h, w2l, bcat, vpom, 192, nullptr);

    // 3) DCNv4 core -> fp16 single plane
    dcn_kernel<<<4096, 256>>>(vpom, dcn);

    // 4) op = dcn @ w_op -> fp32 token-major (the NCHW raw view for step 5)
    gemm_mma<128, 0, false><<<GRID, 256, SM_G4>>>(
        nullptr, dcn, w4h, w4l, zero, op, 128, nullptr);

    // 5) out = (BN2-folded pw1) @ op(NCHW view, fp32 k-major read) -> fp32 NCHW
    gemm_mma<128, 2, true><<<GRID, 256, SM_G5>>>(
        op, nullptr, w5h, w5l, bias1, out, 0, nullptr);
}

// round 12
// speedup vs baseline: 1.4067x; 1.0991x over previous
#include <cuda_runtime.h>
#include <cuda_bf16.h>
#include <cuda_fp16.h>
#include <cstdint>
#include <math.h>

#define DI __device__ __forceinline__
typedef unsigned short u16;

constexpr int TOK = 32768;           // 8 * 64 * 64
constexpr float EPS = 1e-5f;
constexpr int CH = 64;               // tokens per chunk
constexpr int CHUNKS = TOK / CH;     // 512

// ---------------------------------------------------------------------------
// Device scratch
// ---------------------------------------------------------------------------
__device__ __align__(16) u16   g_a2[TOK * 128];        // x1, fp16 single plane
__device__ __align__(16) u16   g_val[TOK * 128];       // value, fp16
__device__ __align__(16) float g_om[TOK * 64];         // offset/mask, fp32 (27 used)
__device__ __align__(16) u16   g_dcn[TOK * 128];       // fp16 single
__device__ __align__(16) float g_op[TOK * 128];        // fp32 token-major

__device__ __align__(16) u16 g_w1h[128 * 128], g_w1l[128 * 128];   // fp16
__device__ __align__(16) u16 g_w2h[192 * 128], g_w2l[192 * 128];   // fp16
__device__ __align__(16) u16 g_w4h[128 * 128], g_w4l[128 * 128];   // fp16
__device__ __align__(16) u16 g_w5h[128 * 128], g_w5l[128 * 128];   // fp16
__device__ float g_bias0[128], g_bias1[128], g_bcat[192], g_zero[192];

// ---------------------------------------------------------------------------
// Helpers
// ---------------------------------------------------------------------------
DI uint32_t smem_u32(const void* p) {
    uint32_t a;
    asm("{ .reg .u64 t; cvta.to.shared.u64 t, %1; cvt.u32.u64 %0, t; }" : "=r"(a) : "l"(p));
    return a;
}

DI void cpa16(uint32_t dst, const void* src) {
    asm volatile("{ .reg .u64 g; cvta.to.global.u64 g, %1; "
                 "cp.async.cg.shared.global [%0], [g], 16; }"
                 :: "r"(dst), "l"(src));
}
DI void cpa_commit() { asm volatile("cp.async.commit_group;" ::: "memory"); }
DI void cpa_wait0() { asm volatile("cp.async.wait_group 0;" ::: "memory"); }
DI void cpa_wait1() { asm volatile("cp.async.wait_group 1;" ::: "memory"); }

DI void ldsm4(uint32_t (&r)[4], uint32_t addr) {
    asm volatile("ldmatrix.sync.aligned.m8n8.x4.shared.b16 {%0,%1,%2,%3}, [%4];"
                 : "=r"(r[0]), "=r"(r[1]), "=r"(r[2]), "=r"(r[3]) : "r"(addr));
}

DI void mma_f16(float (&d)[4], const uint32_t (&a)[4], uint32_t b0, uint32_t b1) {
    asm volatile("mma.sync.aligned.m16n8k16.row.col.f32.f16.f16.f32 "
                 "{%0,%1,%2,%3}, {%4,%5,%6,%7}, {%8,%9}, {%0,%1,%2,%3};"
                 : "+f"(d[0]), "+f"(d[1]), "+f"(d[2]), "+f"(d[3])
                 : "r"(a[0]), "r"(a[1]), "r"(a[2]), "r"(a[3]), "r"(b0), "r"(b1));
}

// XOR-swizzled 16-bit tile: row stride 256 B (128 elems), 16B chunk c -> c ^ (row&7)
DI uint32_t tile_off(int r, int chunk) { return (uint32_t)(r * 256 + ((chunk ^ (r & 7)) << 4)); }

DI uint32_t cvtf16x2(float f0, float f1) {             // {hi=f1, lo=f0}
    uint32_t r;
    asm("cvt.rn.f16x2.f32 %0, %1, %2;" : "=r"(r) : "f"(f1), "f"(f0));
    return r;
}

// ---------------------------------------------------------------------------
// Merged prep: fold BN, transpose to [n][k], split all weights to fp16 hi/lo
// (exact two-term split), plus biases.
// ---------------------------------------------------------------------------
__global__ void prep_all(const float* __restrict__ w_pw0, const float* __restrict__ w_pw1,
                         const float* __restrict__ w_vp,  const float* __restrict__ w_om,
                         const float* __restrict__ w_op,
                         const float* __restrict__ bn1_g, const float* __restrict__ bn1_b,
                         const float* __restrict__ bn1_m, const float* __restrict__ bn1_v,
                         const float* __restrict__ bn2_g, const float* __restrict__ bn2_b,
                         const float* __restrict__ bn2_m, const float* __restrict__ bn2_v,
                         const float* __restrict__ b_vp,  const float* __restrict__ b_om)
{
    int idx = blockIdx.x * blockDim.x + threadIdx.x;
    if (idx < 73728) {
        float w; u16 *H, *L; int off;
        if (idx < 16384) {                       // pw0 * BN1
            int k = idx & 127;
            w = w_pw0[idx] * bn1_g[k] * rsqrtf(bn1_v[k] + EPS);
            H = g_w1h; L = g_w1l; off = idx;
        } else if (idx < 32768) {                // pw1 * BN2
            int j = idx - 16384; int k = j & 127;
            w = w_pw1[j] * bn2_g[k] * rsqrtf(bn2_v[k] + EPS);
            H = g_w5h; L = g_w5l; off = j;
        } else if (idx < 49152) {                // w_op^T
            int j = idx - 32768; int n = j >> 7, k = j & 127;
            w = w_op[k * 128 + n];
            H = g_w4h; L = g_w4l; off = j;
        } else {                                 // [w_vp|w_om]^T padded to 192
            int j = idx - 49152; int n = j >> 7, k = j & 127;
            w = (n < 128) ? w_vp[k * 128 + n] : ((n < 155) ? w_om[k * 32 + (n - 128)] : 0.f);
            H = g_w2h; L = g_w2l; off = j;
        }
        __half h = __float2half_rn(w);
        H[off] = __half_as_ushort(h);
        L[off] = __half_as_ushort(__float2half_rn(w - __half2float(h)));
    } else if (idx < 73856) {
        int o = idx - 73728;
        float s = 0.f;
        for (int c = 0; c < 128; ++c) {
            float sc = bn1_g[c] * rsqrtf(bn1_v[c] + EPS);
            s += w_pw0[o * 128 + c] * (bn1_b[c] - bn1_m[c] * sc);
        }
        g_bias0[o] = s;
    } else if (idx < 73984) {
        int o = idx - 73856;
        float s = 0.f;
        for (int c = 0; c < 128; ++c) {
            float sc = bn2_g[c] * rsqrtf(bn2_v[c] + EPS);
            s += w_pw1[o * 128 + c] * (bn2_b[c] - bn2_m[c] * sc);
        }
        g_bias1[o] = s;
    } else if (idx < 74176) {
        int j = idx - 73984;
        g_bcat[j] = (j < 128) ? b_vp[j] : ((j < 155) ? b_om[j - 128] : 0.f);
        g_zero[j] = 0.f;
    }
}

// ---------------------------------------------------------------------------
// Persistent chunk-loop HMMA GEMM (fp16 2-pass: A single fp16, B exact
// fp16 hi/lo split; fp32 accum).
//  AKM=true : A read fp32 k-major (NCHW raw view); frags via LDS + cvt.
// MODE 0: fp32 row-major reg stores (token-major, ldo)
// MODE 1: raw-reshape scatter (B,C,HW)->(B,HW,C), fp16 single plane out
// MODE 2: fp32 NCHW final output
// MODE 3: split store (N=192): cols 0-127 -> fp16 outH (ld 128);
//         cols 128-191 -> fp32 outF (ld 64). Direct register stores.
// 8 warps = 2m(32) x 4n(N/4); CH=64 chunks, cp.async double buffer.
// ---------------------------------------------------------------------------
template<int N, int MODE, bool AKM>
__global__ void __launch_bounds__(256, 1)
gemm_mma(const float* __restrict__ Af, const u16* __restrict__ A0,
         const u16* __restrict__ B0, const u16* __restrict__ B1,
         const float* __restrict__ biasj,
         float* __restrict__ outF, int ldo, u16* __restrict__ outH)
{
    constexpr int NW = N / 4;
    constexpr int NT = NW / 8;
    constexpr int NP = NW / 16;
    constexpr int BOFF = 2 * N * 256;
    constexpr int ABUF = AKM ? (128 * 272) : (CH * 256);
    constexpr int ldp = N + 1;

    extern __shared__ char sm[];
    const uint32_t uSM = smem_u32(sm);
    const uint32_t uBh = uSM, uBl = uSM + N * 256;
    float* stage = (float*)(sm + BOFF + 2 * ABUF);

    const int t = threadIdx.x, w = t >> 5, l = t & 31;
    const int wm = w & 1, wn = w >> 1;
    const int nb0 = wn * NW;

    const int cbase = (l & 3) * 2;
    float bj0[NT], bj1[NT];
#pragma unroll
    for (int nt = 0; nt < NT; nt++) {
        int col = nb0 + nt * 8 + cbase;
        bj0[nt] = biasj[col];
        bj1[nt] = biasj[col + 1];
    }

    // B load (once)
    {
        const uint4* sh_ = (const uint4*)B0;
        const uint4* sl_ = (const uint4*)B1;
        for (int i = t; i < N * 16; i += 256) {
            int r = i >> 4, c = i & 15;
            uint32_t o = tile_off(r, c);
            cpa16(uBh + o, sh_ + i);
            cpa16(uBl + o, sl_ + i);
        }
    }
    cpa_commit();

    auto loadA = [&](uint32_t dst, int cid_) {
        size_t m0 = (size_t)cid_ * CH;
        if constexpr (AKM) {
            const float* base = Af + (m0 >> 12) * 524288 + (m0 & 4095);
            for (int i = t; i < 2048; i += 256) {
                int k = i >> 4, u = i & 15;
                cpa16(dst + (uint32_t)(k * 272 + u * 16), base + (size_t)k * 4096 + u * 4);
            }
        } else {
            const uint4* s0 = (const uint4*)(A0 + m0 * 128);
            for (int i = t; i < 1024; i += 256) {
                int r = i >> 4, c = i & 15;
                cpa16(dst + tile_off(r, c), s0 + i);
            }
        }
    };

    int cid = blockIdx.x;
    loadA(uSM + BOFF, cid);
    cpa_commit();

    const int arow_lo = wm * 32 + (l & 15);
    const int akhalf = l >> 4;
    const int brow_off = (l & 7) + ((l & 16) >> 1);
    const int bkhalf = (l >> 3) & 1;
    const int mfrag = wm * 32 + (l >> 2);
    const int kfrag = (l & 3) * 2;

    int p = 0;
    while (cid < CHUNKS) {
        const int nxt = cid + (int)gridDim.x;
        const bool hasnext = nxt < CHUNKS;
        if (hasnext) {
            loadA(uSM + BOFF + (p ^ 1) * ABUF, nxt);
            cpa_commit();
            cpa_wait1();
        } else {
            cpa_wait0();
        }
        __syncthreads();

        const uint32_t uA = uSM + BOFF + p * ABUF;
        const float* tileA = (const float*)(sm + BOFF + p * ABUF);

        float d[2][NT][4];
#pragma unroll
        for (int mt = 0; mt < 2; mt++)
#pragma unroll
            for (int nt = 0; nt < NT; nt++)
#pragma unroll
                for (int i = 0; i < 4; i++) d[mt][nt][i] = 0.f;

#pragma unroll
        for (int ks = 0; ks < 8; ks++) {
            uint32_t bh[NP][4], bl[NP][4];
#pragma unroll
            for (int np = 0; np < NP; np++) {
                uint32_t off = tile_off(nb0 + np * 16 + brow_off, 2 * ks + bkhalf);
                ldsm4(bh[np], uBh + off);
                ldsm4(bl[np], uBl + off);
            }
            uint32_t a[2][4];
            if constexpr (AKM) {
#pragma unroll
                for (int mt = 0; mt < 2; mt++) {
                    int mlo = mfrag + mt * 16;
                    int k0 = ks * 16 + kfrag;
                    a[mt][0] = cvtf16x2(tileA[(k0    ) * 68 + mlo],
                                        tileA[(k0 + 1) * 68 + mlo]);
                    a[mt][1] = cvtf16x2(tileA[(k0    ) * 68 + mlo + 8],
                                        tileA[(k0 + 1) * 68 + mlo + 8]);
                    a[mt][2] = cvtf16x2(tileA[(k0 + 8) * 68 + mlo],
                                        tileA[(k0 + 9) * 68 + mlo]);
                    a[mt][3] = cvtf16x2(tileA[(k0 + 8) * 68 + mlo + 8],
                                        tileA[(k0 + 9) * 68 + mlo + 8]);
                }
            } else {
#pragma unroll
                for (int mt = 0; mt < 2; mt++)
                    ldsm4(a[mt], uA + tile_off(arow_lo + mt * 16, 2 * ks + akhalf));
            }
            // pass 1: A*Bh
#pragma unroll
            for (int np = 0; np < NP; np++)
#pragma unroll
                for (int mt = 0; mt < 2; mt++) {
                    mma_f16(d[mt][2 * np],     a[mt], bh[np][0], bh[np][1]);
                    mma_f16(d[mt][2 * np + 1], a[mt], bh[np][2], bh[np][3]);
                }
            // pass 2: A*Bl
#pragma unroll
            for (int np = 0; np < NP; np++)
#pragma unroll
                for (int mt = 0; mt < 2; mt++) {
                    mma_f16(d[mt][2 * np],     a[mt], bl[np][0], bl[np][1]);
                    mma_f16(d[mt][2 * np + 1], a[mt], bl[np][2], bl[np][3]);
                }
        }

        const size_t m0 = (size_t)cid * CH;
        const int rloc = wm * 32 + (l >> 2);

        if (MODE == 0) {
#pragma unroll
            for (int mt = 0; mt < 2; mt++)
#pragma unroll
                for (int nt = 0; nt < NT; nt++) {
                    int row = rloc + mt * 16;
                    int col = nb0 + nt * 8 + cbase;
                    float2 v0 = make_float2(d[mt][nt][0] + bj0[nt], d[mt][nt][1] + bj1[nt]);
                    float2 v1 = make_float2(d[mt][nt][2] + bj0[nt], d[mt][nt][3] + bj1[nt]);
                    *(float2*)(outF + (m0 + row) * (size_t)ldo + col) = v0;
                    *(float2*)(outF + (m0 + row + 8) * (size_t)ldo + col) = v1;
                }
        } else if (MODE == 3) {
            // split: cols<128 -> fp16 outH (ld 128); cols>=128 -> fp32 outF (ld 64)
#pragma unroll
            for (int mt = 0; mt < 2; mt++)
#pragma unroll
                for (int nt = 0; nt < NT; nt++) {
                    int row = rloc + mt * 16;
                    int col = nb0 + nt * 8 + cbase;
                    float v0 = d[mt][nt][0] + bj0[nt], v1 = d[mt][nt][1] + bj1[nt];
                    float v2 = d[mt][nt][2] + bj0[nt], v3 = d[mt][nt][3] + bj1[nt];
                    if (col < 128) {
                        *(uint32_t*)(outH + (m0 + row) * 128 + col)     = cvtf16x2(v0, v1);
                        *(uint32_t*)(outH + (m0 + row + 8) * 128 + col) = cvtf16x2(v2, v3);
                    } else {
                        *(float2*)(outF + (m0 + row) * 64 + (col - 128))     = make_float2(v0, v1);
                        *(float2*)(outF + (m0 + row + 8) * 64 + (col - 128)) = make_float2(v2, v3);
                    }
                }
        } else {
#pragma unroll
            for (int mt = 0; mt < 2; mt++)
#pragma unroll
                for (int nt = 0; nt < NT; nt++) {
                    int row = rloc + mt * 16;
                    int col = nb0 + nt * 8 + cbase;
                    stage[row * ldp + col]           = d[mt][nt][0] + bj0[nt];
                    stage[row * ldp + col + 1]       = d[mt][nt][1] + bj1[nt];
                    stage[(row + 8) * ldp + col]     = d[mt][nt][2] + bj0[nt];
                    stage[(row + 8) * ldp + col + 1] = d[mt][nt][3] + bj1[nt];
                }
            __syncthreads();
            if (MODE == 1) {
                // (B,C,HW)->(B,HW,C) scatter: D[(b,s)][n] -> A'[b*4096+n*32+(s>>7)][s&127]
                const int b  = (int)(m0 >> 12);
                const int sh = (int)((m0 & 4095) >> 7);
                const int cb = (int)(m0 & 64);
                for (int i = t; i < N * 16; i += 256) {
                    int n = i >> 4, q = i & 15, j0 = q * 4;
                    float v0 = stage[(j0 + 0) * ldp + n], v1 = stage[(j0 + 1) * ldp + n];
                    float v2 = stage[(j0 + 2) * ldp + n], v3 = stage[(j0 + 3) * ldp + n];
                    size_t row = (size_t)b * 4096 + (size_t)n * 32 + sh;
                    uint2 o;
                    o.x = cvtf16x2(v0, v1);
                    o.y = cvtf16x2(v2, v3);
                    ((uint2*)(outH + row * 128 + cb))[q] = o;
                }
            } else {
                // NCHW: D[(b, s0+j)][n] -> out[b][n][s0+j]
                const int b  = (int)(m0 >> 12);
                const int s0 = (int)(m0 & 4095);
                for (int i = t; i < N * 16; i += 256) {
                    int n = i >> 4, q = i & 15, j0 = q * 4;
                    float4 v = make_float4(stage[(j0 + 0) * ldp + n], stage[(j0 + 1) * ldp + n],
                                           stage[(j0 + 2) * ldp + n], stage[(j0 + 3) * ldp + n]);
                    *(float4*)(outF + (size_t)b * 524288 + (size_t)n * 4096 + s0 + j0) = v;
                }
            }
        }
        __syncthreads();
        p ^= 1;
        cid = nxt;
    }
}

// ---------------------------------------------------------------------------
// DCNv4 core v3 — setup-broadcast + fp16 value gathers.
// Lanes 0..8 compute bilinear setup for kernel point k=lane; main loop
// shuffles to all lanes; gathers are uint2 (4 fp16 channels per lane).
// ---------------------------------------------------------------------------
__global__ void dcn_kernel(const u16* __restrict__ val, const float* __restrict__ om,
                           u16* __restrict__ oh)
{
    const int warp = threadIdx.x >> 5;
    const int lane = threadIdx.x & 31;
    const int pos  = blockIdx.x * 8 + warp;
    const int b = pos >> 12;
    const int s = pos & 4095;
    const int h = s >> 6;
    const int w = s & 63;

    float omv = (lane < 27) ? om[(size_t)pos * 64 + lane] : 0.f;

    // --- setup (meaningful in lanes 0..8 only) ---
    float w00, w10, w01, w11;
    int   o00, o10, o01, o11;
    {
        const int k = lane;
        const unsigned FULL = 0xffffffffu;
        float dx = __shfl_sync(FULL, omv, (3 * k)     & 31);
        float dy = __shfl_sync(FULL, omv, (3 * k + 1) & 31);
        float m  = __shfl_sync(FULL, omv, (3 * k + 2) & 31);
        int ky = k / 3, kx = k - ky * 3;
        float px = (float)(w + kx - 1) + dx;
        float py = (float)(h + ky - 1) + dy;
        float xf = floorf(px), yf = floorf(py);
        float fx = px - xf, fy = py - yf;
        int x0 = (int)xf, y0 = (int)yf;
        int x1 = x0 + 1,  y1 = y0 + 1;
        float vx0 = (x0 >= 0 && x0 < 64) ? m : 0.f;
        float vx1 = (x1 >= 0 && x1 < 64) ? m : 0.f;
        float gy0 = (y0 >= 0 && y0 < 64) ? 1.f : 0.f;
        float gy1 = (y1 >= 0 && y1 < 64) ? 1.f : 0.f;
        float gx0 = 1.f - fx, gy0f = 1.f - fy;
        w00 = gx0 * gy0f * vx0 * gy0;
        w10 = fx  * gy0f * vx1 * gy0;
        w01 = gx0 * fy   * vx0 * gy1;
        w11 = fx  * fy   * vx1 * gy1;
        int xc0 = min(max(x0, 0), 63), xc1 = min(max(x1, 0), 63);
        int yc0 = min(max(y0, 0), 63), yc1 = min(max(y1, 0), 63);
        o00 = (yc0 * 64 + xc0) * 128;
        o10 = (yc0 * 64 + xc1) * 128;
        o01 = (yc1 * 64 + xc0) * 128;
        o11 = (yc1 * 64 + xc1) * 128;
    }

    const u16* vbc = val + (((size_t)b << 12) * 128) + (lane << 2);
    float4 acc = make_float4(0.f, 0.f, 0.f, 0.f);
    const unsigned FULL = 0xffffffffu;

#pragma unroll
    for (int k = 0; k < 9; ++k) {
        int   a0 = __shfl_sync(FULL, o00, k);
        int   a1 = __shfl_sync(FULL, o10, k);
        int   a2 = __shfl_sync(FULL, o01, k);
        int   a3 = __shfl_sync(FULL, o11, k);
        float t0 = __shfl_sync(FULL, w00, k);
        float t1 = __shfl_sync(FULL, w10, k);
        float t2 = __shfl_sync(FULL, w01, k);
        float t3 = __shfl_sync(FULL, w11, k);
        uint2 r0 = *(const uint2*)(vbc + a0);
        uint2 r1 = *(const uint2*)(vbc + a1);
        uint2 r2 = *(const uint2*)(vbc + a2);
        uint2 r3 = *(const uint2*)(vbc + a3);
        float2 f0a = __half22float2(*(__half2*)&r0.x), f0b = __half22float2(*(__half2*)&r0.y);
        float2 f1a = __half22float2(*(__half2*)&r1.x), f1b = __half22float2(*(__half2*)&r1.y);
        float2 f2a = __half22float2(*(__half2*)&r2.x), f2b = __half22float2(*(__half2*)&r2.y);
        float2 f3a = __half22float2(*(__half2*)&r3.x), f3b = __half22float2(*(__half2*)&r3.y);
        acc.x += t0 * f0a.x; acc.y += t0 * f0a.y; acc.z += t0 * f0b.x; acc.w += t0 * f0b.y;
        acc.x += t1 * f1a.x; acc.y += t1 * f1a.y; acc.z += t1 * f1b.x; acc.w += t1 * f1b.y;
        acc.x += t2 * f2a.x; acc.y += t2 * f2a.y; acc.z += t2 * f2b.x; acc.w += t2 * f2b.y;
        acc.x += t3 * f3a.x; acc.y += t3 * f3a.y; acc.z += t3 * f3b.x; acc.w += t3 * f3b.y;
    }
    uint2 o;
    o.x = cvtf16x2(acc.x, acc.y);
    o.y = cvtf16x2(acc.z, acc.w);
    *(uint2*)(oh + (size_t)pos * 128 + (lane << 2)) = o;
}

// ---------------------------------------------------------------------------
// Launcher
// ---------------------------------------------------------------------------
extern "C" void kernel_launch(void* const* d_in, const int* in_sizes, int n_in,
                              void* d_out, int out_size)
{
    (void)in_sizes; (void)n_in; (void)out_size;
    const float* x     = (const float*)d_in[0];
    const float* bn1_g = (const float*)d_in[1];
    const float* bn1_b = (const float*)d_in[2];
    const float* bn1_m = (const float*)d_in[3];
    const float* bn1_v = (const float*)d_in[4];
    const float* w_pw0 = (const float*)d_in[5];
    const float* w_vp  = (const float*)d_in[6];
    const float* b_vp  = (const float*)d_in[7];
    const float* w_om  = (const float*)d_in[8];
    const float* b_om  = (const float*)d_in[9];
    const float* w_op  = (const float*)d_in[10];
    const float* bn2_g = (const float*)d_in[11];
    const float* bn2_b = (const float*)d_in[12];
    const float* bn2_m = (const float*)d_in[13];
    const float* bn2_v = (const float*)d_in[14];
    const float* w_pw1 = (const float*)d_in[15];
    float* out = (float*)d_out;

    u16 *a2, *val, *dcn;
    u16 *w1h, *w1l, *w2h, *w2l, *w4h, *w4l, *w5h, *w5l;
    float *omb, *op, *bias0, *bias1, *bcat, *zero;
    cudaGetSymbolAddress((void**)&a2, g_a2);
    cudaGetSymbolAddress((void**)&val, g_val);    cudaGetSymbolAddress((void**)&omb, g_om);
    cudaGetSymbolAddress((void**)&dcn, g_dcn);    cudaGetSymbolAddress((void**)&op, g_op);
    cudaGetSymbolAddress((void**)&w1h, g_w1h);    cudaGetSymbolAddress((void**)&w1l, g_w1l);
    cudaGetSymbolAddress((void**)&w2h, g_w2h);    cudaGetSymbolAddress((void**)&w2l, g_w2l);
    cudaGetSymbolAddress((void**)&w4h, g_w4h);    cudaGetSymbolAddress((void**)&w4l, g_w4l);
    cudaGetSymbolAddress((void**)&w5h, g_w5h);    cudaGetSymbolAddress((void**)&w5l, g_w5l);
    cudaGetSymbolAddress((void**)&bias0, g_bias0); cudaGetSymbolAddress((void**)&bias1, g_bias1);
    cudaGetSymbolAddress((void**)&bcat, g_bcat);  cudaGetSymbolAddress((void**)&zero, g_zero);

    // smem: B(2*N*256) + A dbuf + stage (MODE1/2 only)
    const int SM_G1 = 65536 + 2 * 128 * 272 + 64 * 129 * 4;     // gemm1 (AKM, MODE1)
    const int SM_G2 = 98304 + 2 * 64 * 256;                     // gemm2 (MODE3)
    const int SM_G4 = 65536 + 2 * 64 * 256;                     // gemm4 (MODE0)
    const int SM_G5 = 65536 + 2 * 128 * 272 + 64 * 129 * 4;     // gemm5 (AKM, MODE2)
    cudaFuncSetAttribute((const void*)gemm_mma<128, 1, true>,
                         cudaFuncAttributeMaxDynamicSharedMemorySize, SM_G1);
    cudaFuncSetAttribute((const void*)gemm_mma<192, 3, false>,
                         cudaFuncAttributeMaxDynamicSharedMemorySize, SM_G2);
    cudaFuncSetAttribute((const void*)gemm_mma<128, 0, false>,
                         cudaFuncAttributeMaxDynamicSharedMemorySize, SM_G4);
    cudaFuncSetAttribute((const void*)gemm_mma<128, 2, true>,
                         cudaFuncAttributeMaxDynamicSharedMemorySize, SM_G5);

    const int GRID = 148;

    prep_all<<<290, 256>>>(w_pw0, w_pw1, w_vp, w_om, w_op,
                           bn1_g, bn1_b, bn1_m, bn1_v,
                           bn2_g, bn2_b, bn2_m, bn2_v, b_vp, b_om);

    // 1) x1 = x(NCHW fp32 k-major) @ w1^T + bias0 -> fp16 single scatter
    gemm_mma<128, 1, true><<<GRID, 256, SM_G1>>>(
        x, nullptr, w1h, w1l, bias0, nullptr, 0, a2);

    // 2) vpom split: value -> fp16 g_val, offset/mask -> fp32 g_om (ld 64)
    gemm_mma<192, 3, false><<<GRID, 256, SM_G2>>>(
        nullptr, a2, w2h, w2l, bcat, omb, 0, val);

    // 3) DCNv4 core (fp16 gathers) -> fp16 single plane
    dcn_kernel<<<4096, 256>>>(val, omb, dcn);

    // 4) op = dcn @ w_op -> fp32 token-major (the NCHW raw view for step 5)
    gemm_mma<128, 0, false><<<GRID, 256, SM_G4>>>(
        nullptr, dcn, w4h, w4l, zero, op, 128, nullptr);

    // 5) out = (BN2-folded pw1) @ op(NCHW view, fp32 k-major read) -> fp32 NCHW
    gemm_mma<128, 2, true><<<GRID, 256, SM_G5>>>(
        op, nullptr, w5h, w5l, bias1, out, 0, nullptr);
}

// round 13
// speedup vs baseline: 1.4421x; 1.0252x over previous
#include <cuda_runtime.h>
#include <cuda_bf16.h>
#include <cuda_fp16.h>
#include <cstdint>
#include <math.h>

#define DI __device__ __forceinline__
typedef unsigned short u16;

constexpr int TOK = 32768;           // 8 * 64 * 64
constexpr float EPS = 1e-5f;
constexpr int CH = 64;               // tokens per chunk
constexpr int CHUNKS = TOK / CH;     // 512

// ---------------------------------------------------------------------------
// Device scratch
// ---------------------------------------------------------------------------
__device__ __align__(16) u16   g_a2[TOK * 128];        // x1, fp16 single plane
__device__ __align__(16) u16   g_val[TOK * 128];       // value, fp16
__device__ __align__(16) float g_om[TOK * 64];         // offset/mask, fp32 (27 used)
__device__ __align__(16) u16   g_dcn[TOK * 128];       // fp16 single
__device__ __align__(16) float g_op[TOK * 128];        // fp32 token-major

__device__ __align__(16) u16 g_w1h[128 * 128], g_w1l[128 * 128];   // fp16
__device__ __align__(16) u16 g_w2h[192 * 128], g_w2l[192 * 128];   // fp16
__device__ __align__(16) u16 g_w4h[128 * 128], g_w4l[128 * 128];   // fp16
__device__ __align__(16) u16 g_w5h[128 * 128], g_w5l[128 * 128];   // fp16
__device__ float g_bias0[128], g_bias1[128], g_bcat[192], g_zero[192];

// ---------------------------------------------------------------------------
// Helpers
// ---------------------------------------------------------------------------
DI uint32_t smem_u32(const void* p) {
    uint32_t a;
    asm("{ .reg .u64 t; cvta.to.shared.u64 t, %1; cvt.u32.u64 %0, t; }" : "=r"(a) : "l"(p));
    return a;
}

DI void cpa16(uint32_t dst, const void* src) {
    asm volatile("{ .reg .u64 g; cvta.to.global.u64 g, %1; "
                 "cp.async.cg.shared.global [%0], [g], 16; }"
                 :: "r"(dst), "l"(src));
}
DI void cpa_commit() { asm volatile("cp.async.commit_group;" ::: "memory"); }
DI void cpa_wait0() { asm volatile("cp.async.wait_group 0;" ::: "memory"); }
DI void cpa_wait1() { asm volatile("cp.async.wait_group 1;" ::: "memory"); }

DI void ldsm4(uint32_t (&r)[4], uint32_t addr) {
    asm volatile("ldmatrix.sync.aligned.m8n8.x4.shared.b16 {%0,%1,%2,%3}, [%4];"
                 : "=r"(r[0]), "=r"(r[1]), "=r"(r[2]), "=r"(r[3]) : "r"(addr));
}

DI void mma_f16(float (&d)[4], const uint32_t (&a)[4], uint32_t b0, uint32_t b1) {
    asm volatile("mma.sync.aligned.m16n8k16.row.col.f32.f16.f16.f32 "
                 "{%0,%1,%2,%3}, {%4,%5,%6,%7}, {%8,%9}, {%0,%1,%2,%3};"
                 : "+f"(d[0]), "+f"(d[1]), "+f"(d[2]), "+f"(d[3])
                 : "r"(a[0]), "r"(a[1]), "r"(a[2]), "r"(a[3]), "r"(b0), "r"(b1));
}

// XOR-swizzled 16-bit tile: row stride 256 B (128 elems), 16B chunk c -> c ^ (row&7)
DI uint32_t tile_off(int r, int chunk) { return (uint32_t)(r * 256 + ((chunk ^ (r & 7)) << 4)); }

DI uint32_t cvtf16x2(float f0, float f1) {             // {hi=f1, lo=f0}
    uint32_t r;
    asm("cvt.rn.f16x2.f32 %0, %1, %2;" : "=r"(r) : "f"(f1), "f"(f0));
    return r;
}

// ---------------------------------------------------------------------------
// Merged prep: fold BN, transpose to [n][k], split all weights to fp16 hi/lo
// (exact two-term split), plus biases.
// ---------------------------------------------------------------------------
__global__ void prep_all(const float* __restrict__ w_pw0, const float* __restrict__ w_pw1,
                         const float* __restrict__ w_vp,  const float* __restrict__ w_om,
                         const float* __restrict__ w_op,
                         const float* __restrict__ bn1_g, const float* __restrict__ bn1_b,
                         const float* __restrict__ bn1_m, const float* __restrict__ bn1_v,
                         const float* __restrict__ bn2_g, const float* __restrict__ bn2_b,
                         const float* __restrict__ bn2_m, const float* __restrict__ bn2_v,
                         const float* __restrict__ b_vp,  const float* __restrict__ b_om)
{
    int idx = blockIdx.x * blockDim.x + threadIdx.x;
    if (idx < 73728) {
        float w; u16 *H, *L; int off;
        if (idx < 16384) {                       // pw0 * BN1
            int k = idx & 127;
            w = w_pw0[idx] * bn1_g[k] * rsqrtf(bn1_v[k] + EPS);
            H = g_w1h; L = g_w1l; off = idx;
        } else if (idx < 32768) {                // pw1 * BN2
            int j = idx - 16384; int k = j & 127;
            w = w_pw1[j] * bn2_g[k] * rsqrtf(bn2_v[k] + EPS);
            H = g_w5h; L = g_w5l; off = j;
        } else if (idx < 49152) {                // w_op^T
            int j = idx - 32768; int n = j >> 7, k = j & 127;
            w = w_op[k * 128 + n];
            H = g_w4h; L = g_w4l; off = j;
        } else {                                 // [w_vp|w_om]^T padded to 192
            int j = idx - 49152; int n = j >> 7, k = j & 127;
            w = (n < 128) ? w_vp[k * 128 + n] : ((n < 155) ? w_om[k * 32 + (n - 128)] : 0.f);
            H = g_w2h; L = g_w2l; off = j;
        }
        __half h = __float2half_rn(w);
        H[off] = __half_as_ushort(h);
        L[off] = __half_as_ushort(__float2half_rn(w - __half2float(h)));
    } else if (idx < 73856) {
        int o = idx - 73728;
        float s = 0.f;
        for (int c = 0; c < 128; ++c) {
            float sc = bn1_g[c] * rsqrtf(bn1_v[c] + EPS);
            s += w_pw0[o * 128 + c] * (bn1_b[c] - bn1_m[c] * sc);
        }
        g_bias0[o] = s;
    } else if (idx < 73984) {
        int o = idx - 73856;
        float s = 0.f;
        for (int c = 0; c < 128; ++c) {
            float sc = bn2_g[c] * rsqrtf(bn2_v[c] + EPS);
            s += w_pw1[o * 128 + c] * (bn2_b[c] - bn2_m[c] * sc);
        }
        g_bias1[o] = s;
    } else if (idx < 74176) {
        int j = idx - 73984;
        g_bcat[j] = (j < 128) ? b_vp[j] : ((j < 155) ? b_om[j - 128] : 0.f);
        g_zero[j] = 0.f;
    }
}

// ---------------------------------------------------------------------------
// Persistent chunk-loop HMMA GEMM (fp16 2-pass: A single fp16, B exact
// fp16 hi/lo split; fp32 accum).
//  AKM=true : A read fp32 k-major (NCHW raw view); frags via LDS + cvt.
// MODE 0: fp32 row-major reg stores (token-major, ldo)
// MODE 1: raw-reshape scatter (B,C,HW)->(B,HW,C), fp16 single plane out
// MODE 2: fp32 NCHW final output
// MODE 3: split store (N=192): cols 0-127 -> fp16 outH (ld 128);
//         cols 128-191 -> fp32 outF (ld 64). Direct register stores.
// 8 warps = 2m(32) x 4n(N/4); CH=64 chunks, cp.async double buffer.
// ---------------------------------------------------------------------------
template<int N, int MODE, bool AKM>
__global__ void __launch_bounds__(256, 1)
gemm_mma(const float* __restrict__ Af, const u16* __restrict__ A0,
         const u16* __restrict__ B0, const u16* __restrict__ B1,
         const float* __restrict__ biasj,
         float* __restrict__ outF, int ldo, u16* __restrict__ outH)
{
    constexpr int NW = N / 4;
    constexpr int NT = NW / 8;
    constexpr int NP = NW / 16;
    constexpr int BOFF = 2 * N * 256;
    constexpr int ABUF = AKM ? (128 * 272) : (CH * 256);
    constexpr int ldp = N + 1;

    extern __shared__ char sm[];
    const uint32_t uSM = smem_u32(sm);
    const uint32_t uBh = uSM, uBl = uSM + N * 256;
    float* stage = (float*)(sm + BOFF + 2 * ABUF);

    const int t = threadIdx.x, w = t >> 5, l = t & 31;
    const int wm = w & 1, wn = w >> 1;
    const int nb0 = wn * NW;

    const int cbase = (l & 3) * 2;
    float bj0[NT], bj1[NT];
#pragma unroll
    for (int nt = 0; nt < NT; nt++) {
        int col = nb0 + nt * 8 + cbase;
        bj0[nt] = biasj[col];
        bj1[nt] = biasj[col + 1];
    }

    // B load (once)
    {
        const uint4* sh_ = (const uint4*)B0;
        const uint4* sl_ = (const uint4*)B1;
        for (int i = t; i < N * 16; i += 256) {
            int r = i >> 4, c = i & 15;
            uint32_t o = tile_off(r, c);
            cpa16(uBh + o, sh_ + i);
            cpa16(uBl + o, sl_ + i);
        }
    }
    cpa_commit();

    auto loadA = [&](uint32_t dst, int cid_) {
        size_t m0 = (size_t)cid_ * CH;
        if constexpr (AKM) {
            const float* base = Af + (m0 >> 12) * 524288 + (m0 & 4095);
            for (int i = t; i < 2048; i += 256) {
                int k = i >> 4, u = i & 15;
                cpa16(dst + (uint32_t)(k * 272 + u * 16), base + (size_t)k * 4096 + u * 4);
            }
        } else {
            const uint4* s0 = (const uint4*)(A0 + m0 * 128);
            for (int i = t; i < 1024; i += 256) {
                int r = i >> 4, c = i & 15;
                cpa16(dst + tile_off(r, c), s0 + i);
            }
        }
    };

    int cid = blockIdx.x;
    loadA(uSM + BOFF, cid);
    cpa_commit();

    const int arow_lo = wm * 32 + (l & 15);
    const int akhalf = l >> 4;
    const int brow_off = (l & 7) + ((l & 16) >> 1);
    const int bkhalf = (l >> 3) & 1;
    const int mfrag = wm * 32 + (l >> 2);
    const int kfrag = (l & 3) * 2;

    int p = 0;
    while (cid < CHUNKS) {
        const int nxt = cid + (int)gridDim.x;
        const bool hasnext = nxt < CHUNKS;
        if (hasnext) {
            loadA(uSM + BOFF + (p ^ 1) * ABUF, nxt);
            cpa_commit();
            cpa_wait1();
        } else {
            cpa_wait0();
        }
        __syncthreads();

        const uint32_t uA = uSM + BOFF + p * ABUF;
        const float* tileA = (const float*)(sm + BOFF + p * ABUF);

        float d[2][NT][4];
#pragma unroll
        for (int mt = 0; mt < 2; mt++)
#pragma unroll
            for (int nt = 0; nt < NT; nt++)
#pragma unroll
                for (int i = 0; i < 4; i++) d[mt][nt][i] = 0.f;

#pragma unroll
        for (int ks = 0; ks < 8; ks++) {
            uint32_t bh[NP][4], bl[NP][4];
#pragma unroll
            for (int np = 0; np < NP; np++) {
                uint32_t off = tile_off(nb0 + np * 16 + brow_off, 2 * ks + bkhalf);
                ldsm4(bh[np], uBh + off);
                ldsm4(bl[np], uBl + off);
            }
            uint32_t a[2][4];
            if constexpr (AKM) {
#pragma unroll
                for (int mt = 0; mt < 2; mt++) {
                    int mlo = mfrag + mt * 16;
                    int k0 = ks * 16 + kfrag;
                    a[mt][0] = cvtf16x2(tileA[(k0    ) * 68 + mlo],
                                        tileA[(k0 + 1) * 68 + mlo]);
                    a[mt][1] = cvtf16x2(tileA[(k0    ) * 68 + mlo + 8],
                                        tileA[(k0 + 1) * 68 + mlo + 8]);
                    a[mt][2] = cvtf16x2(tileA[(k0 + 8) * 68 + mlo],
                                        tileA[(k0 + 9) * 68 + mlo]);
                    a[mt][3] = cvtf16x2(tileA[(k0 + 8) * 68 + mlo + 8],
                                        tileA[(k0 + 9) * 68 + mlo + 8]);
                }
            } else {
#pragma unroll
                for (int mt = 0; mt < 2; mt++)
                    ldsm4(a[mt], uA + tile_off(arow_lo + mt * 16, 2 * ks + akhalf));
            }
            // pass 1: A*Bh
#pragma unroll
            for (int np = 0; np < NP; np++)
#pragma unroll
                for (int mt = 0; mt < 2; mt++) {
                    mma_f16(d[mt][2 * np],     a[mt], bh[np][0], bh[np][1]);
                    mma_f16(d[mt][2 * np + 1], a[mt], bh[np][2], bh[np][3]);
                }
            // pass 2: A*Bl
#pragma unroll
            for (int np = 0; np < NP; np++)
#pragma unroll
                for (int mt = 0; mt < 2; mt++) {
                    mma_f16(d[mt][2 * np],     a[mt], bl[np][0], bl[np][1]);
                    mma_f16(d[mt][2 * np + 1], a[mt], bl[np][2], bl[np][3]);
                }
        }

        const size_t m0 = (size_t)cid * CH;
        const int rloc = wm * 32 + (l >> 2);

        if (MODE == 0) {
#pragma unroll
            for (int mt = 0; mt < 2; mt++)
#pragma unroll
                for (int nt = 0; nt < NT; nt++) {
                    int row = rloc + mt * 16;
                    int col = nb0 + nt * 8 + cbase;
                    float2 v0 = make_float2(d[mt][nt][0] + bj0[nt], d[mt][nt][1] + bj1[nt]);
                    float2 v1 = make_float2(d[mt][nt][2] + bj0[nt], d[mt][nt][3] + bj1[nt]);
                    *(float2*)(outF + (m0 + row) * (size_t)ldo + col) = v0;
                    *(float2*)(outF + (m0 + row + 8) * (size_t)ldo + col) = v1;
                }
        } else if (MODE == 3) {
            // split: cols<128 -> fp16 outH (ld 128); cols>=128 -> fp32 outF (ld 64)
#pragma unroll
            for (int mt = 0; mt < 2; mt++)
#pragma unroll
                for (int nt = 0; nt < NT; nt++) {
                    int row = rloc + mt * 16;
                    int col = nb0 + nt * 8 + cbase;
                    float v0 = d[mt][nt][0] + bj0[nt], v1 = d[mt][nt][1] + bj1[nt];
                    float v2 = d[mt][nt][2] + bj0[nt], v3 = d[mt][nt][3] + bj1[nt];
                    if (col < 128) {
                        *(uint32_t*)(outH + (m0 + row) * 128 + col)     = cvtf16x2(v0, v1);
                        *(uint32_t*)(outH + (m0 + row + 8) * 128 + col) = cvtf16x2(v2, v3);
                    } else {
                        *(float2*)(outF + (m0 + row) * 64 + (col - 128))     = make_float2(v0, v1);
                        *(float2*)(outF + (m0 + row + 8) * 64 + (col - 128)) = make_float2(v2, v3);
                    }
                }
        } else {
#pragma unroll
            for (int mt = 0; mt < 2; mt++)
#pragma unroll
                for (int nt = 0; nt < NT; nt++) {
                    int row = rloc + mt * 16;
                    int col = nb0 + nt * 8 + cbase;
                    stage[row * ldp + col]           = d[mt][nt][0] + bj0[nt];
                    stage[row * ldp + col + 1]       = d[mt][nt][1] + bj1[nt];
                    stage[(row + 8) * ldp + col]     = d[mt][nt][2] + bj0[nt];
                    stage[(row + 8) * ldp + col + 1] = d[mt][nt][3] + bj1[nt];
                }
            __syncthreads();
            if (MODE == 1) {
                const int b  = (int)(m0 >> 12);
                const int sh = (int)((m0 & 4095) >> 7);
                const int cb = (int)(m0 & 64);
                for (int i = t; i < N * 16; i += 256) {
                    int n = i >> 4, q = i & 15, j0 = q * 4;
                    float v0 = stage[(j0 + 0) * ldp + n], v1 = stage[(j0 + 1) * ldp + n];
                    float v2 = stage[(j0 + 2) * ldp + n], v3 = stage[(j0 + 3) * ldp + n];
                    size_t row = (size_t)b * 4096 + (size_t)n * 32 + sh;
                    uint2 o;
                    o.x = cvtf16x2(v0, v1);
                    o.y = cvtf16x2(v2, v3);
                    ((uint2*)(outH + row * 128 + cb))[q] = o;
                }
            } else {
                const int b  = (int)(m0 >> 12);
                const int s0 = (int)(m0 & 4095);
                for (int i = t; i < N * 16; i += 256) {
                    int n = i >> 4, q = i & 15, j0 = q * 4;
                    float4 v = make_float4(stage[(j0 + 0) * ldp + n], stage[(j0 + 1) * ldp + n],
                                           stage[(j0 + 2) * ldp + n], stage[(j0 + 3) * ldp + n]);
                    *(float4*)(outF + (size_t)b * 524288 + (size_t)n * 4096 + s0 + j0) = v;
                }
            }
        }
        __syncthreads();
        p ^= 1;
        cid = nxt;
    }
}

// ---------------------------------------------------------------------------
// DCNv4 core v4 — setup-broadcast + fp16 gathers + half2 interpolation.
// ---------------------------------------------------------------------------
__global__ void dcn_kernel(const u16* __restrict__ val, const float* __restrict__ om,
                           u16* __restrict__ oh)
{
    const int warp = threadIdx.x >> 5;
    const int lane = threadIdx.x & 31;
    const int pos  = blockIdx.x * 8 + warp;
    const int b = pos >> 12;
    const int s = pos & 4095;
    const int h = s >> 6;
    const int w = s & 63;

    float omv = (lane < 27) ? om[(size_t)pos * 64 + lane] : 0.f;

    // --- setup (meaningful in lanes 0..8 only) ---
    uint32_t wb00, wb10, wb01, wb11;       // broadcast half2 weights
    int      o00, o10, o01, o11;
    {
        const int k = lane;
        const unsigned FULL = 0xffffffffu;
        float dx = __shfl_sync(FULL, omv, (3 * k)     & 31);
        float dy = __shfl_sync(FULL, omv, (3 * k + 1) & 31);
        float m  = __shfl_sync(FULL, omv, (3 * k + 2) & 31);
        int ky = k / 3, kx = k - ky * 3;
        float px = (float)(w + kx - 1) + dx;
        float py = (float)(h + ky - 1) + dy;
        float xf = floorf(px), yf = floorf(py);
        float fx = px - xf, fy = py - yf;
        int x0 = (int)xf, y0 = (int)yf;
        int x1 = x0 + 1,  y1 = y0 + 1;
        float vx0 = (x0 >= 0 && x0 < 64) ? m : 0.f;
        float vx1 = (x1 >= 0 && x1 < 64) ? m : 0.f;
        float gy0 = (y0 >= 0 && y0 < 64) ? 1.f : 0.f;
        float gy1 = (y1 >= 0 && y1 < 64) ? 1.f : 0.f;
        float gx0 = 1.f - fx, gy0f = 1.f - fy;
        float w00 = gx0 * gy0f * vx0 * gy0;
        float w10 = fx  * gy0f * vx1 * gy0;
        float w01 = gx0 * fy   * vx0 * gy1;
        float w11 = fx  * fy   * vx1 * gy1;
        wb00 = cvtf16x2(w00, w00);
        wb10 = cvtf16x2(w10, w10);
        wb01 = cvtf16x2(w01, w01);
        wb11 = cvtf16x2(w11, w11);
        int xc0 = min(max(x0, 0), 63), xc1 = min(max(x1, 0), 63);
        int yc0 = min(max(y0, 0), 63), yc1 = min(max(y1, 0), 63);
        o00 = (yc0 * 64 + xc0) * 128;
        o10 = (yc0 * 64 + xc1) * 128;
        o01 = (yc1 * 64 + xc0) * 128;
        o11 = (yc1 * 64 + xc1) * 128;
    }

    const u16* vbc = val + (((size_t)b << 12) * 128) + (lane << 2);
    float4 acc = make_float4(0.f, 0.f, 0.f, 0.f);
    const unsigned FULL = 0xffffffffu;

#pragma unroll
    for (int k = 0; k < 9; ++k) {
        int a0 = __shfl_sync(FULL, o00, k);
        int a1 = __shfl_sync(FULL, o10, k);
        int a2 = __shfl_sync(FULL, o01, k);
        int a3 = __shfl_sync(FULL, o11, k);
        uint32_t u0 = __shfl_sync(FULL, wb00, k);
        uint32_t u1 = __shfl_sync(FULL, wb10, k);
        uint32_t u2 = __shfl_sync(FULL, wb01, k);
        uint32_t u3 = __shfl_sync(FULL, wb11, k);
        uint2 r0 = *(const uint2*)(vbc + a0);
        uint2 r1 = *(const uint2*)(vbc + a1);
        uint2 r2 = *(const uint2*)(vbc + a2);
        uint2 r3 = *(const uint2*)(vbc + a3);
        __half2 h0 = *(__half2*)&u0, h1 = *(__half2*)&u1;
        __half2 h2 = *(__half2*)&u2, h3 = *(__half2*)&u3;
        __half2 pa = __hmul2(h0, *(__half2*)&r0.x);
        __half2 pb = __hmul2(h0, *(__half2*)&r0.y);
        pa = __hfma2(h1, *(__half2*)&r1.x, pa);
        pb = __hfma2(h1, *(__half2*)&r1.y, pb);
        pa = __hfma2(h2, *(__half2*)&r2.x, pa);
        pb = __hfma2(h2, *(__half2*)&r2.y, pb);
        pa = __hfma2(h3, *(__half2*)&r3.x, pa);
        pb = __hfma2(h3, *(__half2*)&r3.y, pb);
        float2 fa = __half22float2(pa);
        float2 fb = __half22float2(pb);
        acc.x += fa.x; acc.y += fa.y; acc.z += fb.x; acc.w += fb.y;
    }
    uint2 o;
    o.x = cvtf16x2(acc.x, acc.y);
    o.y = cvtf16x2(acc.z, acc.w);
    *(uint2*)(oh + (size_t)pos * 128 + (lane << 2)) = o;
}

// ---------------------------------------------------------------------------
// Launcher
// ---------------------------------------------------------------------------
extern "C" void kernel_launch(void* const* d_in, const int* in_sizes, int n_in,
                              void* d_out, int out_size)
{
    (void)in_sizes; (void)n_in; (void)out_size;
    const float* x     = (const float*)d_in[0];
    const float* bn1_g = (const float*)d_in[1];
    const float* bn1_b = (const float*)d_in[2];
    const float* bn1_m = (const float*)d_in[3];
    const float* bn1_v = (const float*)d_in[4];
    const float* w_pw0 = (const float*)d_in[5];
    const float* w_vp  = (const float*)d_in[6];
    const float* b_vp  = (const float*)d_in[7];
    const float* w_om  = (const float*)d_in[8];
    const float* b_om  = (const float*)d_in[9];
    const float* w_op  = (const float*)d_in[10];
    const float* bn2_g = (const float*)d_in[11];
    const float* bn2_b = (const float*)d_in[12];
    const float* bn2_m = (const float*)d_in[13];
    const float* bn2_v = (const float*)d_in[14];
    const float* w_pw1 = (const float*)d_in[15];
    float* out = (float*)d_out;

    u16 *a2, *val, *dcn;
    u16 *w1h, *w1l, *w2h, *w2l, *w4h, *w4l, *w5h, *w5l;
    float *omb, *op, *bias0, *bias1, *bcat, *zero;
    cudaGetSymbolAddress((void**)&a2, g_a2);
    cudaGetSymbolAddress((void**)&val, g_val);    cudaGetSymbolAddress((void**)&omb, g_om);
    cudaGetSymbolAddress((void**)&dcn, g_dcn);    cudaGetSymbolAddress((void**)&op, g_op);
    cudaGetSymbolAddress((void**)&w1h, g_w1h);    cudaGetSymbolAddress((void**)&w1l, g_w1l);
    cudaGetSymbolAddress((void**)&w2h, g_w2h);    cudaGetSymbolAddress((void**)&w2l, g_w2l);
    cudaGetSymbolAddress((void**)&w4h, g_w4h);    cudaGetSymbolAddress((void**)&w4l, g_w4l);
    cudaGetSymbolAddress((void**)&w5h, g_w5h);    cudaGetSymbolAddress((void**)&w5l, g_w5l);
    cudaGetSymbolAddress((void**)&bias0, g_bias0); cudaGetSymbolAddress((void**)&bias1, g_bias1);
    cudaGetSymbolAddress((void**)&bcat, g_bcat);  cudaGetSymbolAddress((void**)&zero, g_zero);

    const int SM_G1 = 65536 + 2 * 128 * 272 + 64 * 129 * 4;
    const int SM_G2 = 98304 + 2 * 64 * 256;
    const int SM_G4 = 65536 + 2 * 64 * 256;
    const int SM_G5 = 65536 + 2 * 128 * 272 + 64 * 129 * 4;
    cudaFuncSetAttribute((const void*)gemm_mma<128, 1, true>,
                         cudaFuncAttributeMaxDynamicSharedMemorySize, SM_G1);
    cudaFuncSetAttribute((const void*)gemm_mma<192, 3, false>,
                         cudaFuncAttributeMaxDynamicSharedMemorySize, SM_G2);
    cudaFuncSetAttribute((const void*)gemm_mma<128, 0, false>,
                         cudaFuncAttributeMaxDynamicSharedMemorySize, SM_G4);
    cudaFuncSetAttribute((const void*)gemm_mma<128, 2, true>,
                         cudaFuncAttributeMaxDynamicSharedMemorySize, SM_G5);

    const int GRID = 148;

    prep_all<<<290, 256>>>(w_pw0, w_pw1, w_vp, w_om, w_op,
                           bn1_g, bn1_b, bn1_m, bn1_v,
                           bn2_g, bn2_b, bn2_m, bn2_v, b_vp, b_om);

    gemm_mma<128, 1, true><<<GRID, 256, SM_G1>>>(
        x, nullptr, w1h, w1l, bias0, nullptr, 0, a2);

    gemm_mma<192, 3, false><<<GRID, 256, SM_G2>>>(
        nullptr, a2, w2h, w2l, bcat, omb, 0, val);

    dcn_kernel<<<4096, 256>>>(val, omb, dcn);

    gemm_mma<128, 0, false><<<GRID, 256, SM_G4>>>(
        nullptr, dcn, w4h, w4l, zero, op, 128, nullptr);

    gemm_mma<128, 2, true><<<GRID, 256, SM_G5>>>(
        op, nullptr, w5h, w5l, bias1, out, 0, nullptr);
}